// round 2
// baseline (speedup 1.0000x reference)
#include <cuda_runtime.h>
#include <math.h>

#define Bz  4
#define Sz  2048
#define Dz  1024
#define Hz  16
#define DHz 64
#define BSz (Bz*Sz)          /* 8192 rows */

// ---- scratch (no allocation allowed; __device__ globals) ----
__device__ float g_Q[(size_t)BSz * Hz * DHz];
__device__ float g_K[(size_t)BSz * Hz * DHz];
__device__ float g_V[(size_t)BSz * Hz * DHz];
__device__ float g_Z[(size_t)BSz * Hz * DHz];

// ============================================================================
// SGEMM: C[M,N] = A[M,K] @ B[K,N] + bias[N]
// PROJ=true : B is W (H, D, DH) viewed as Bmat[k][n] = W[n>>6][k][n&63]
// PROJ=false: B is row-major (K, N)
// 128x128 tile, BK=8, 256 threads, 8x8 micro-tile.
// ============================================================================
template <bool PROJ>
__global__ __launch_bounds__(256) void sgemm_kernel(
    const float* __restrict__ A, const float* __restrict__ Bm,
    const float* __restrict__ bias, float* __restrict__ C,
    int M, int N, int K)
{
    __shared__ float As[8][132];   // padded: avoids store-bank conflicts
    __shared__ float Bs[8][128];

    const int t  = threadIdx.x;
    const int m0 = blockIdx.y * 128;
    const int n0 = blockIdx.x * 128;
    const int tm = t >> 4, tn = t & 15;
    const int ar = t >> 1, ac = (t & 1) * 4;
    const int br = t >> 5, bc = (t & 31) * 4;

    float acc[8][8] = {};

    for (int k0 = 0; k0 < K; k0 += 8) {
        // A tile (transposed store)
        float4 av = *(const float4*)(A + (size_t)(m0 + ar) * K + k0 + ac);
        As[ac + 0][ar] = av.x; As[ac + 1][ar] = av.y;
        As[ac + 2][ar] = av.z; As[ac + 3][ar] = av.w;

        // B tile
        const float* bp;
        if (PROJ) {
            int n = n0 + bc;
            bp = Bm + (size_t)(n >> 6) * ((size_t)K * 64)
                    + (size_t)(k0 + br) * 64 + (n & 63);
        } else {
            bp = Bm + (size_t)(k0 + br) * N + n0 + bc;
        }
        *(float4*)&Bs[br][bc] = *(const float4*)bp;

        __syncthreads();
        #pragma unroll
        for (int kk = 0; kk < 8; ++kk) {
            float a[8], b[8];
            *(float4*)(a)     = *(float4*)&As[kk][tm * 8];
            *(float4*)(a + 4) = *(float4*)&As[kk][tm * 8 + 4];
            *(float4*)(b)     = *(float4*)&Bs[kk][tn * 8];
            *(float4*)(b + 4) = *(float4*)&Bs[kk][tn * 8 + 4];
            #pragma unroll
            for (int i = 0; i < 8; ++i)
                #pragma unroll
                for (int j = 0; j < 8; ++j)
                    acc[i][j] = fmaf(a[i], b[j], acc[i][j]);
        }
        __syncthreads();
    }

    #pragma unroll
    for (int i = 0; i < 8; ++i) {
        size_t row = (size_t)(m0 + tm * 8 + i);
        #pragma unroll
        for (int j = 0; j < 8; j += 4) {
            int n = n0 + tn * 8 + j;
            float4 v;
            v.x = acc[i][j + 0] + bias[n + 0];
            v.y = acc[i][j + 1] + bias[n + 1];
            v.z = acc[i][j + 2] + bias[n + 2];
            v.w = acc[i][j + 3] + bias[n + 3];
            *(float4*)(C + row * N + n) = v;
        }
    }
}

// ============================================================================
// Causal flash attention, fp32. One CTA = 64 q-rows of one (b,h).
// 256 threads as 16x16, 4x4 micro-tiles for both S=Q@K^T and O+=P@V.
// Online softmax stats (m,l) live in smem; causal k-tile loop pruned.
// ============================================================================
#define ATT_P 68            /* smem pitch (floats): float4-aligned, conflict-lean */
#define ATT_SMEM ((4 * 64 * ATT_P + 3 * 64) * 4)

__global__ __launch_bounds__(256) void attn_kernel(
    const float* __restrict__ gQ, const float* __restrict__ gK,
    const float* __restrict__ gV, float* __restrict__ gZ)
{
    extern __shared__ float sm[];
    float* Qs       = sm;                       // [64][ATT_P] (q, dh)
    float* KsT      = Qs  + 64 * ATT_P;         // [64][ATT_P] (dh, key)  transposed
    float* Vs       = KsT + 64 * ATT_P;         // [64][ATT_P] (key, dh)
    float* Ps       = Vs  + 64 * ATT_P;         // scores / probs (q, key)
    float* sm_m     = Ps  + 64 * ATT_P;
    float* sm_l     = sm_m + 64;
    float* sm_scale = sm_l + 64;

    const int t   = threadIdx.x;
    const int q0  = blockIdx.x * 64;
    const int b   = blockIdx.y >> 4;
    const int h   = blockIdx.y & 15;
    const size_t base = (size_t)b * Sz * Hz * DHz + (size_t)h * DHz;
    const int rs = Hz * DHz;                    // 1024

    const int tm = t >> 4, tn = t & 15;
    const int lr = t >> 2, lc0 = (t & 3) * 16;  // loader: 4 threads/row

    if (t < 64) { sm_m[t] = -1e30f; sm_l[t] = 0.f; }

    {   // Q tile
        const float* src = gQ + base + (size_t)(q0 + lr) * rs + lc0;
        #pragma unroll
        for (int i = 0; i < 4; ++i)
            *(float4*)&Qs[lr * ATT_P + lc0 + i * 4] = *(const float4*)(src + i * 4);
    }
    float o[4][4] = {};
    const int ntiles = (q0 >> 6) + 1;           // causal prune
    __syncthreads();

    for (int kt = 0; kt < ntiles; ++kt) {
        const int k0 = kt << 6;
        {   // K (transposed) + V tiles
            const float* sk = gK + base + (size_t)(k0 + lr) * rs + lc0;
            const float* sv = gV + base + (size_t)(k0 + lr) * rs + lc0;
            #pragma unroll
            for (int i = 0; i < 4; ++i) {
                float4 kv = *(const float4*)(sk + i * 4);
                int c = lc0 + i * 4;
                KsT[(c + 0) * ATT_P + lr] = kv.x;
                KsT[(c + 1) * ATT_P + lr] = kv.y;
                KsT[(c + 2) * ATT_P + lr] = kv.z;
                KsT[(c + 3) * ATT_P + lr] = kv.w;
                *(float4*)&Vs[lr * ATT_P + c] = *(const float4*)(sv + i * 4);
            }
        }
        __syncthreads();

        // S = Q @ K^T
        float s[4][4] = {};
        #pragma unroll
        for (int kk = 0; kk < 64; ++kk) {
            float a[4];
            #pragma unroll
            for (int i = 0; i < 4; ++i) a[i] = Qs[(tm * 4 + i) * ATT_P + kk];
            float4 bv = *(float4*)&KsT[kk * ATT_P + tn * 4];
            #pragma unroll
            for (int i = 0; i < 4; ++i) {
                s[i][0] = fmaf(a[i], bv.x, s[i][0]);
                s[i][1] = fmaf(a[i], bv.y, s[i][1]);
                s[i][2] = fmaf(a[i], bv.z, s[i][2]);
                s[i][3] = fmaf(a[i], bv.w, s[i][3]);
            }
        }
        // scale + causal mask + stash
        #pragma unroll
        for (int i = 0; i < 4; ++i) {
            int qg = q0 + tm * 4 + i;
            #pragma unroll
            for (int j = 0; j < 4; ++j) {
                int kg = k0 + tn * 4 + j;
                float v = s[i][j] * 0.125f;           // 1/sqrt(64)
                Ps[(tm * 4 + i) * ATT_P + tn * 4 + j] = (kg > qg) ? -1e30f : v;
            }
        }
        __syncthreads();

        // online softmax over the 64-wide tile (4 threads per row)
        {
            const int sub = t & 3;
            float mx = -1e30f;
            #pragma unroll
            for (int c = 0; c < 16; ++c)
                mx = fmaxf(mx, Ps[lr * ATT_P + lc0 + c]);
            mx = fmaxf(mx, __shfl_xor_sync(0xffffffffu, mx, 1));
            mx = fmaxf(mx, __shfl_xor_sync(0xffffffffu, mx, 2));
            float m_old = sm_m[lr];
            float m_new = fmaxf(m_old, mx);
            float sum = 0.f;
            #pragma unroll
            for (int c = 0; c < 16; ++c) {
                float p = __expf(Ps[lr * ATT_P + lc0 + c] - m_new);
                Ps[lr * ATT_P + lc0 + c] = p;
                sum += p;
            }
            sum += __shfl_xor_sync(0xffffffffu, sum, 1);
            sum += __shfl_xor_sync(0xffffffffu, sum, 2);
            if (sub == 0) {
                float corr = __expf(m_old - m_new);
                sm_scale[lr] = corr;
                sm_l[lr] = sm_l[lr] * corr + sum;
                sm_m[lr] = m_new;
            }
        }
        __syncthreads();

        // O = O*corr + P @ V
        float scv[4];
        #pragma unroll
        for (int i = 0; i < 4; ++i) scv[i] = sm_scale[tm * 4 + i];
        #pragma unroll
        for (int i = 0; i < 4; ++i)
            #pragma unroll
            for (int j = 0; j < 4; ++j) o[i][j] *= scv[i];
        #pragma unroll
        for (int kk = 0; kk < 64; ++kk) {
            float p[4];
            #pragma unroll
            for (int i = 0; i < 4; ++i) p[i] = Ps[(tm * 4 + i) * ATT_P + kk];
            float4 vv = *(float4*)&Vs[kk * ATT_P + tn * 4];
            #pragma unroll
            for (int i = 0; i < 4; ++i) {
                o[i][0] = fmaf(p[i], vv.x, o[i][0]);
                o[i][1] = fmaf(p[i], vv.y, o[i][1]);
                o[i][2] = fmaf(p[i], vv.z, o[i][2]);
                o[i][3] = fmaf(p[i], vv.w, o[i][3]);
            }
        }
        __syncthreads();    // protect KsT/Vs/Ps before next tile
    }

    #pragma unroll
    for (int i = 0; i < 4; ++i) {
        float inv = 1.f / sm_l[tm * 4 + i];
        float4 v = make_float4(o[i][0] * inv, o[i][1] * inv,
                               o[i][2] * inv, o[i][3] * inv);
        *(float4*)(gZ + base + (size_t)(q0 + tm * 4 + i) * rs + tn * 4) = v;
    }
}

// ============================================================================
extern "C" void kernel_launch(void* const* d_in, const int* in_sizes, int n_in,
                              void* d_out, int out_size)
{
    (void)in_sizes; (void)n_in; (void)out_size;
    const float* x  = (const float*)d_in[0];
    const float* WQ = (const float*)d_in[1];
    const float* bQ = (const float*)d_in[2];
    const float* WK = (const float*)d_in[3];
    const float* bK = (const float*)d_in[4];
    const float* WV = (const float*)d_in[5];
    const float* bV = (const float*)d_in[6];
    const float* WO = (const float*)d_in[7];
    const float* bO = (const float*)d_in[8];
    float* out = (float*)d_out;

    float *pQ, *pK, *pV, *pZ;
    cudaGetSymbolAddress((void**)&pQ, g_Q);
    cudaGetSymbolAddress((void**)&pK, g_K);
    cudaGetSymbolAddress((void**)&pV, g_V);
    cudaGetSymbolAddress((void**)&pZ, g_Z);

    dim3 blk(256);
    dim3 gproj((Hz * DHz) / 128, BSz / 128);      // 8 x 64
    sgemm_kernel<true><<<gproj, blk>>>(x, WQ, bQ, pQ, BSz, Hz * DHz, Dz);
    sgemm_kernel<true><<<gproj, blk>>>(x, WK, bK, pK, BSz, Hz * DHz, Dz);
    sgemm_kernel<true><<<gproj, blk>>>(x, WV, bV, pV, BSz, Hz * DHz, Dz);

    cudaFuncSetAttribute(attn_kernel,
                         cudaFuncAttributeMaxDynamicSharedMemorySize, ATT_SMEM);
    attn_kernel<<<dim3(Sz / 64, Bz * Hz), blk, ATT_SMEM>>>(pQ, pK, pV, pZ);

    dim3 gout(Dz / 128, BSz / 128);               // 8 x 64
    sgemm_kernel<false><<<gout, blk>>>(pZ, WO, bO, out, BSz, Dz, Hz * DHz);
}

// round 6
// speedup vs baseline: 1.5843x; 1.5843x over previous
#include <cuda_runtime.h>
#include <math.h>

#define Bz  4
#define Sz  2048
#define Dz  1024
#define Hz  16
#define DHz 64
#define BSz (Bz*Sz)          /* 8192 rows */

// ---- scratch (no allocation allowed; __device__ globals) ----
__device__ float g_Q[(size_t)BSz * Hz * DHz];
__device__ float g_K[(size_t)BSz * Hz * DHz];
__device__ float g_V[(size_t)BSz * Hz * DHz];
__device__ float g_Z[(size_t)BSz * Hz * DHz];

// ============================================================================
// TF32 tensor-core GEMM: C[M,N] = A[M,K] @ B[K,N] + bias[N]
// PROJ=true : B is W (H, D, DH) viewed as Bmat[k][n] = W[n>>6][k][n&63]
// 128x128 tile, BK=32, 256 threads (8 warps as 2x4, each 64x32),
// mma.sync.m16n8k8.tf32, cp.async double buffer.
// Smem banking: A pitch 36 -> frag-load bank = 4*gid+tig = lane (conflict-free)
//               B pitch 136 -> frag-load bank = 8*tig+gid = lane (conflict-free)
// ============================================================================
#define AP 36
#define BP 136
#define ASZ (128 * AP)
#define BSZ (32 * BP)
#define GEMM_SMEM ((ASZ + BSZ) * 2 * 4)

__device__ __forceinline__ unsigned f2tf(float f) {
    unsigned u;
    asm("cvt.rna.tf32.f32 %0, %1;" : "=r"(u) : "f"(f));
    return u;
}

template <bool PROJ>
__global__ __launch_bounds__(256) void tf32_gemm(
    const float* __restrict__ A, const float* __restrict__ Bm,
    const float* __restrict__ bias, float* __restrict__ C,
    int M, int N, int K)
{
    extern __shared__ float smx[];
    float* Asb[2] = { smx, smx + ASZ };
    float* Bsb[2] = { smx + 2 * ASZ, smx + 2 * ASZ + BSZ };

    const int t    = threadIdx.x;
    const int warp = t >> 5, lane = t & 31;
    const int gid  = lane >> 2, tig = lane & 3;
    const int wm   = warp >> 2, wn = warp & 3;          // 2 x 4 warp grid
    const int m0   = blockIdx.y * 128, n0 = blockIdx.x * 128;
    const int lr   = t >> 3, lc = (t & 7) * 4;          // tile loader lanes

    float acc[4][4][4] = {};
    const int NT = K / 32;                              // 32 for K=1024

    for (int tile = 0; tile <= NT; ++tile) {
        if (tile < NT) {
            const int k0 = tile * 32;
            const int buf = tile & 1;
            float* ad = Asb[buf];
            #pragma unroll
            for (int i = 0; i < 4; ++i) {
                int r = lr + 32 * i;
                unsigned s = (unsigned)__cvta_generic_to_shared(ad + r * AP + lc);
                const float* g = A + (size_t)(m0 + r) * K + k0 + lc;
                asm volatile("cp.async.ca.shared.global [%0], [%1], 16;\n"
                             :: "r"(s), "l"(g));
            }
            float* bd = Bsb[buf];
            #pragma unroll
            for (int i = 0; i < 4; ++i) {
                int n = lc + 32 * i;
                unsigned s = (unsigned)__cvta_generic_to_shared(bd + lr * BP + n);
                const float* g;
                if (PROJ) {
                    int ng = n0 + n;
                    g = Bm + (size_t)(ng >> 6) * ((size_t)K * 64)
                           + (size_t)(k0 + lr) * 64 + (ng & 63);
                } else {
                    g = Bm + (size_t)(k0 + lr) * N + n0 + n;
                }
                asm volatile("cp.async.ca.shared.global [%0], [%1], 16;\n"
                             :: "r"(s), "l"(g));
            }
            asm volatile("cp.async.commit_group;\n");
        }
        if (tile == 0) continue;
        if (tile < NT) asm volatile("cp.async.wait_group 1;\n");
        else           asm volatile("cp.async.wait_group 0;\n");
        __syncthreads();

        const int buf = (tile - 1) & 1;
        const float* as = Asb[buf];
        const float* bs = Bsb[buf];
        #pragma unroll
        for (int ks = 0; ks < 4; ++ks) {
            const int kk = ks * 8;
            unsigned af[4][4];
            #pragma unroll
            for (int mf = 0; mf < 4; ++mf) {
                const float* ap = as + (wm * 64 + mf * 16 + gid) * AP + kk + tig;
                af[mf][0] = f2tf(ap[0]);
                af[mf][1] = f2tf(ap[8 * AP]);
                af[mf][2] = f2tf(ap[4]);
                af[mf][3] = f2tf(ap[8 * AP + 4]);
            }
            unsigned bf[4][2];
            #pragma unroll
            for (int nf = 0; nf < 4; ++nf) {
                const float* bp = bs + (kk + tig) * BP + wn * 32 + nf * 8 + gid;
                bf[nf][0] = f2tf(bp[0]);
                bf[nf][1] = f2tf(bp[4 * BP]);
            }
            #pragma unroll
            for (int mf = 0; mf < 4; ++mf)
                #pragma unroll
                for (int nf = 0; nf < 4; ++nf)
                    asm volatile(
                        "mma.sync.aligned.m16n8k8.row.col.f32.tf32.tf32.f32 "
                        "{%0,%1,%2,%3}, {%4,%5,%6,%7}, {%8,%9}, {%0,%1,%2,%3};\n"
                        : "+f"(acc[mf][nf][0]), "+f"(acc[mf][nf][1]),
                          "+f"(acc[mf][nf][2]), "+f"(acc[mf][nf][3])
                        : "r"(af[mf][0]), "r"(af[mf][1]),
                          "r"(af[mf][2]), "r"(af[mf][3]),
                          "r"(bf[nf][0]), "r"(bf[nf][1]));
        }
        __syncthreads();
    }

    // epilogue: c0/c1 at (row, col 2*tig(+1)); c2/c3 at row+8
    #pragma unroll
    for (int mf = 0; mf < 4; ++mf) {
        int r0 = m0 + wm * 64 + mf * 16 + gid;
        #pragma unroll
        for (int nf = 0; nf < 4; ++nf) {
            int c = n0 + wn * 32 + nf * 8 + tig * 2;
            float b0v = bias[c], b1v = bias[c + 1];
            float2 v0 = make_float2(acc[mf][nf][0] + b0v, acc[mf][nf][1] + b1v);
            float2 v1 = make_float2(acc[mf][nf][2] + b0v, acc[mf][nf][3] + b1v);
            *(float2*)(C + (size_t)r0 * N + c)       = v0;
            *(float2*)(C + (size_t)(r0 + 8) * N + c) = v1;
        }
    }
}

// ============================================================================
// Causal flash attention, fp32 (unchanged — known good at 2958us total).
// ============================================================================
#define ATT_P 68
#define ATT_SMEM ((4 * 64 * ATT_P + 3 * 64) * 4)

__global__ __launch_bounds__(256) void attn_kernel(
    const float* __restrict__ gQ, const float* __restrict__ gK,
    const float* __restrict__ gV, float* __restrict__ gZ)
{
    extern __shared__ float sm[];
    float* Qs       = sm;
    float* KsT      = Qs  + 64 * ATT_P;
    float* Vs       = KsT + 64 * ATT_P;
    float* Ps       = Vs  + 64 * ATT_P;
    float* sm_m     = Ps  + 64 * ATT_P;
    float* sm_l     = sm_m + 64;
    float* sm_scale = sm_l + 64;

    const int t   = threadIdx.x;
    const int q0  = blockIdx.x * 64;
    const int b   = blockIdx.y >> 4;
    const int h   = blockIdx.y & 15;
    const size_t base = (size_t)b * Sz * Hz * DHz + (size_t)h * DHz;
    const int rs = Hz * DHz;

    const int tm = t >> 4, tn = t & 15;
    const int lr = t >> 2, lc0 = (t & 3) * 16;

    if (t < 64) { sm_m[t] = -1e30f; sm_l[t] = 0.f; }

    {
        const float* src = gQ + base + (size_t)(q0 + lr) * rs + lc0;
        #pragma unroll
        for (int i = 0; i < 4; ++i)
            *(float4*)&Qs[lr * ATT_P + lc0 + i * 4] = *(const float4*)(src + i * 4);
    }
    float o[4][4] = {};
    const int ntiles = (q0 >> 6) + 1;
    __syncthreads();

    for (int kt = 0; kt < ntiles; ++kt) {
        const int k0 = kt << 6;
        {
            const float* sk = gK + base + (size_t)(k0 + lr) * rs + lc0;
            const float* sv = gV + base + (size_t)(k0 + lr) * rs + lc0;
            #pragma unroll
            for (int i = 0; i < 4; ++i) {
                float4 kv = *(const float4*)(sk + i * 4);
                int c = lc0 + i * 4;
                KsT[(c + 0) * ATT_P + lr] = kv.x;
                KsT[(c + 1) * ATT_P + lr] = kv.y;
                KsT[(c + 2) * ATT_P + lr] = kv.z;
                KsT[(c + 3) * ATT_P + lr] = kv.w;
                *(float4*)&Vs[lr * ATT_P + c] = *(const float4*)(sv + i * 4);
            }
        }
        __syncthreads();

        float s[4][4] = {};
        #pragma unroll
        for (int kk = 0; kk < 64; ++kk) {
            float a[4];
            #pragma unroll
            for (int i = 0; i < 4; ++i) a[i] = Qs[(tm * 4 + i) * ATT_P + kk];
            float4 bv = *(float4*)&KsT[kk * ATT_P + tn * 4];
            #pragma unroll
            for (int i = 0; i < 4; ++i) {
                s[i][0] = fmaf(a[i], bv.x, s[i][0]);
                s[i][1] = fmaf(a[i], bv.y, s[i][1]);
                s[i][2] = fmaf(a[i], bv.z, s[i][2]);
                s[i][3] = fmaf(a[i], bv.w, s[i][3]);
            }
        }
        #pragma unroll
        for (int i = 0; i < 4; ++i) {
            int qg = q0 + tm * 4 + i;
            #pragma unroll
            for (int j = 0; j < 4; ++j) {
                int kg = k0 + tn * 4 + j;
                float v = s[i][j] * 0.125f;
                Ps[(tm * 4 + i) * ATT_P + tn * 4 + j] = (kg > qg) ? -1e30f : v;
            }
        }
        __syncthreads();

        {
            const int sub = t & 3;
            float mx = -1e30f;
            #pragma unroll
            for (int c = 0; c < 16; ++c)
                mx = fmaxf(mx, Ps[lr * ATT_P + lc0 + c]);
            mx = fmaxf(mx, __shfl_xor_sync(0xffffffffu, mx, 1));
            mx = fmaxf(mx, __shfl_xor_sync(0xffffffffu, mx, 2));
            float m_old = sm_m[lr];
            float m_new = fmaxf(m_old, mx);
            float sum = 0.f;
            #pragma unroll
            for (int c = 0; c < 16; ++c) {
                float p = __expf(Ps[lr * ATT_P + lc0 + c] - m_new);
                Ps[lr * ATT_P + lc0 + c] = p;
                sum += p;
            }
            sum += __shfl_xor_sync(0xffffffffu, sum, 1);
            sum += __shfl_xor_sync(0xffffffffu, sum, 2);
            if (sub == 0) {
                float corr = __expf(m_old - m_new);
                sm_scale[lr] = corr;
                sm_l[lr] = sm_l[lr] * corr + sum;
                sm_m[lr] = m_new;
            }
        }
        __syncthreads();

        float scv[4];
        #pragma unroll
        for (int i = 0; i < 4; ++i) scv[i] = sm_scale[tm * 4 + i];
        #pragma unroll
        for (int i = 0; i < 4; ++i)
            #pragma unroll
            for (int j = 0; j < 4; ++j) o[i][j] *= scv[i];
        #pragma unroll
        for (int kk = 0; kk < 64; ++kk) {
            float p[4];
            #pragma unroll
            for (int i = 0; i < 4; ++i) p[i] = Ps[(tm * 4 + i) * ATT_P + kk];
            float4 vv = *(float4*)&Vs[kk * ATT_P + tn * 4];
            #pragma unroll
            for (int i = 0; i < 4; ++i) {
                o[i][0] = fmaf(p[i], vv.x, o[i][0]);
                o[i][1] = fmaf(p[i], vv.y, o[i][1]);
                o[i][2] = fmaf(p[i], vv.z, o[i][2]);
                o[i][3] = fmaf(p[i], vv.w, o[i][3]);
            }
        }
        __syncthreads();
    }

    #pragma unroll
    for (int i = 0; i < 4; ++i) {
        float inv = 1.f / sm_l[tm * 4 + i];
        float4 v = make_float4(o[i][0] * inv, o[i][1] * inv,
                               o[i][2] * inv, o[i][3] * inv);
        *(float4*)(gZ + base + (size_t)(q0 + tm * 4 + i) * rs + tn * 4) = v;
    }
}

// ============================================================================
extern "C" void kernel_launch(void* const* d_in, const int* in_sizes, int n_in,
                              void* d_out, int out_size)
{
    (void)in_sizes; (void)n_in; (void)out_size;
    const float* x  = (const float*)d_in[0];
    const float* WQ = (const float*)d_in[1];
    const float* bQ = (const float*)d_in[2];
    const float* WK = (const float*)d_in[3];
    const float* bK = (const float*)d_in[4];
    const float* WV = (const float*)d_in[5];
    const float* bV = (const float*)d_in[6];
    const float* WO = (const float*)d_in[7];
    const float* bO = (const float*)d_in[8];
    float* out = (float*)d_out;

    float *pQ, *pK, *pV, *pZ;
    cudaGetSymbolAddress((void**)&pQ, g_Q);
    cudaGetSymbolAddress((void**)&pK, g_K);
    cudaGetSymbolAddress((void**)&pV, g_V);
    cudaGetSymbolAddress((void**)&pZ, g_Z);

    // Unconditional every call (no static guards — harness contract).
    // These are attribute sets, not stream ops: graph-capture safe.
    cudaFuncSetAttribute(tf32_gemm<true>,
                         cudaFuncAttributeMaxDynamicSharedMemorySize, GEMM_SMEM);
    cudaFuncSetAttribute(tf32_gemm<false>,
                         cudaFuncAttributeMaxDynamicSharedMemorySize, GEMM_SMEM);
    cudaFuncSetAttribute(attn_kernel,
                         cudaFuncAttributeMaxDynamicSharedMemorySize, ATT_SMEM);

    dim3 blk(256);
    dim3 gproj((Hz * DHz) / 128, BSz / 128);      // 8 x 64
    tf32_gemm<true><<<gproj, blk, GEMM_SMEM>>>(x, WQ, bQ, pQ, BSz, Hz * DHz, Dz);
    tf32_gemm<true><<<gproj, blk, GEMM_SMEM>>>(x, WK, bK, pK, BSz, Hz * DHz, Dz);
    tf32_gemm<true><<<gproj, blk, GEMM_SMEM>>>(x, WV, bV, pV, BSz, Hz * DHz, Dz);

    attn_kernel<<<dim3(Sz / 64, Bz * Hz), blk, ATT_SMEM>>>(pQ, pK, pV, pZ);

    dim3 gout(Dz / 128, BSz / 128);               // 8 x 64
    tf32_gemm<false><<<gout, blk, GEMM_SMEM>>>(pZ, WO, bO, out, BSz, Dz, Hz * DHz);
}

// round 10
// speedup vs baseline: 2.2916x; 1.4464x over previous
#include <cuda_runtime.h>
#include <math.h>

#define Bz  4
#define Sz  2048
#define Dz  1024
#define Hz  16
#define DHz 64
#define BSz (Bz*Sz)          /* 8192 rows */

// ---- scratch (no allocation allowed; __device__ globals) ----
__device__ float g_Q[(size_t)BSz * Hz * DHz];
__device__ float g_K[(size_t)BSz * Hz * DHz];
__device__ float g_V[(size_t)BSz * Hz * DHz];
__device__ float g_Z[(size_t)BSz * Hz * DHz];

__device__ __forceinline__ unsigned f2tf(float f) {
    unsigned u;
    asm("cvt.rna.tf32.f32 %0, %1;" : "=r"(u) : "f"(f));
    return u;
}

__device__ __forceinline__ void mma_tf32(float* c,
    unsigned a0, unsigned a1, unsigned a2, unsigned a3,
    unsigned b0, unsigned b1)
{
    asm volatile(
        "mma.sync.aligned.m16n8k8.row.col.f32.tf32.tf32.f32 "
        "{%0,%1,%2,%3}, {%4,%5,%6,%7}, {%8,%9}, {%0,%1,%2,%3};\n"
        : "+f"(c[0]), "+f"(c[1]), "+f"(c[2]), "+f"(c[3])
        : "r"(a0), "r"(a1), "r"(a2), "r"(a3), "r"(b0), "r"(b1));
}

// ============================================================================
// TF32 tensor-core GEMM: C[M,N] = A[M,K] @ B[K,N] + bias[N]   (validated R6)
// ============================================================================
#define AP 36
#define BP 136
#define ASZ (128 * AP)
#define BSZ (32 * BP)
#define GEMM_SMEM ((ASZ + BSZ) * 2 * 4)

template <bool PROJ>
__global__ __launch_bounds__(256) void tf32_gemm(
    const float* __restrict__ A, const float* __restrict__ Bm,
    const float* __restrict__ bias, float* __restrict__ C,
    int M, int N, int K)
{
    extern __shared__ float smx[];
    float* Asb[2] = { smx, smx + ASZ };
    float* Bsb[2] = { smx + 2 * ASZ, smx + 2 * ASZ + BSZ };

    const int t    = threadIdx.x;
    const int warp = t >> 5, lane = t & 31;
    const int gid  = lane >> 2, tig = lane & 3;
    const int wm   = warp >> 2, wn = warp & 3;
    const int m0   = blockIdx.y * 128, n0 = blockIdx.x * 128;
    const int lr   = t >> 3, lc = (t & 7) * 4;

    float acc[4][4][4] = {};
    const int NT = K / 32;

    for (int tile = 0; tile <= NT; ++tile) {
        if (tile < NT) {
            const int k0 = tile * 32;
            const int buf = tile & 1;
            float* ad = Asb[buf];
            #pragma unroll
            for (int i = 0; i < 4; ++i) {
                int r = lr + 32 * i;
                unsigned s = (unsigned)__cvta_generic_to_shared(ad + r * AP + lc);
                const float* g = A + (size_t)(m0 + r) * K + k0 + lc;
                asm volatile("cp.async.ca.shared.global [%0], [%1], 16;\n"
                             :: "r"(s), "l"(g));
            }
            float* bd = Bsb[buf];
            #pragma unroll
            for (int i = 0; i < 4; ++i) {
                int n = lc + 32 * i;
                unsigned s = (unsigned)__cvta_generic_to_shared(bd + lr * BP + n);
                const float* g;
                if (PROJ) {
                    int ng = n0 + n;
                    g = Bm + (size_t)(ng >> 6) * ((size_t)K * 64)
                           + (size_t)(k0 + lr) * 64 + (ng & 63);
                } else {
                    g = Bm + (size_t)(k0 + lr) * N + n0 + n;
                }
                asm volatile("cp.async.ca.shared.global [%0], [%1], 16;\n"
                             :: "r"(s), "l"(g));
            }
            asm volatile("cp.async.commit_group;\n");
        }
        if (tile == 0) continue;
        if (tile < NT) asm volatile("cp.async.wait_group 1;\n");
        else           asm volatile("cp.async.wait_group 0;\n");
        __syncthreads();

        const int buf = (tile - 1) & 1;
        const float* as = Asb[buf];
        const float* bs = Bsb[buf];
        #pragma unroll
        for (int ks = 0; ks < 4; ++ks) {
            const int kk = ks * 8;
            unsigned af[4][4];
            #pragma unroll
            for (int mf = 0; mf < 4; ++mf) {
                const float* ap = as + (wm * 64 + mf * 16 + gid) * AP + kk + tig;
                af[mf][0] = f2tf(ap[0]);
                af[mf][1] = f2tf(ap[8 * AP]);
                af[mf][2] = f2tf(ap[4]);
                af[mf][3] = f2tf(ap[8 * AP + 4]);
            }
            unsigned bf[4][2];
            #pragma unroll
            for (int nf = 0; nf < 4; ++nf) {
                const float* bp = bs + (kk + tig) * BP + wn * 32 + nf * 8 + gid;
                bf[nf][0] = f2tf(bp[0]);
                bf[nf][1] = f2tf(bp[4 * BP]);
            }
            #pragma unroll
            for (int mf = 0; mf < 4; ++mf)
                #pragma unroll
                for (int nf = 0; nf < 4; ++nf)
                    mma_tf32(acc[mf][nf], af[mf][0], af[mf][1], af[mf][2],
                             af[mf][3], bf[nf][0], bf[nf][1]);
        }
        __syncthreads();
    }

    #pragma unroll
    for (int mf = 0; mf < 4; ++mf) {
        int r0 = m0 + wm * 64 + mf * 16 + gid;
        #pragma unroll
        for (int nf = 0; nf < 4; ++nf) {
            int c = n0 + wn * 32 + nf * 8 + tig * 2;
            float b0v = bias[c], b1v = bias[c + 1];
            float2 v0 = make_float2(acc[mf][nf][0] + b0v, acc[mf][nf][1] + b1v);
            float2 v1 = make_float2(acc[mf][nf][2] + b0v, acc[mf][nf][3] + b1v);
            *(float2*)(C + (size_t)r0 * N + c)       = v0;
            *(float2*)(C + (size_t)(r0 + 8) * N + c) = v1;
        }
    }
}

// ============================================================================
// Causal flash attention with tf32 tensor cores.
// CTA = 64 q-rows of one (b,h). 8 warps: wq=warp>>1 (16 q-rows each),
// wh=warp&1 (32 k-cols for S; 32 dh-cols for PV).
// Smem holds tf32 bit patterns for Q/K/V (cvt at load; 0.125 folded into Q).
// Pitches: Q/K/P = 68 -> frag bank 4g+t conflict-free; V = 72 -> bank 8t+g.
// Softmax identical to validated fp32 version; P stored as tf32 after exp.
// ============================================================================
#define ATQ 68
#define ATV 72
#define ATT_SMEM ((64 * ATQ * 3 + 64 * ATV + 3 * 64) * 4)

__global__ __launch_bounds__(256) void attn_tc_kernel(
    const float* __restrict__ gQ, const float* __restrict__ gK,
    const float* __restrict__ gV, float* __restrict__ gZ)
{
    extern __shared__ float sm[];
    float* Qs       = sm;                        // [64][ATQ] tf32 bits
    float* Ks       = Qs + 64 * ATQ;             // [64][ATQ] tf32 bits
    float* Ps       = Ks + 64 * ATQ;             // [64][ATQ] scores -> tf32 probs
    float* Vs       = Ps + 64 * ATQ;             // [64][ATV] tf32 bits
    float* sm_m     = Vs + 64 * ATV;
    float* sm_l     = sm_m + 64;
    float* sm_scale = sm_l + 64;

    const int t    = threadIdx.x;
    const int warp = t >> 5, lane = t & 31;
    const int gid  = lane >> 2, tig = lane & 3;
    const int wq   = warp >> 1, wh = warp & 1;
    const int q0   = blockIdx.x * 64;
    const int b    = blockIdx.y >> 4;
    const int h    = blockIdx.y & 15;
    const size_t base = (size_t)b * Sz * Hz * DHz + (size_t)h * DHz;
    const int rs   = Hz * DHz;                   // 1024
    const int lr   = t >> 2, lc0 = (t & 3) * 16;

    if (t < 64) { sm_m[t] = -1e30f; sm_l[t] = 0.f; }

    {   // Q tile: scale by 1/8 (exact) then cvt to tf32
        const float* src = gQ + base + (size_t)(q0 + lr) * rs + lc0;
        unsigned* qd = (unsigned*)&Qs[lr * ATQ + lc0];
        #pragma unroll
        for (int i = 0; i < 4; ++i) {
            float4 v = *(const float4*)(src + i * 4);
            qd[i * 4 + 0] = f2tf(v.x * 0.125f);
            qd[i * 4 + 1] = f2tf(v.y * 0.125f);
            qd[i * 4 + 2] = f2tf(v.z * 0.125f);
            qd[i * 4 + 3] = f2tf(v.w * 0.125f);
        }
    }
    float acco[4][4] = {};
    const int ntiles = (q0 >> 6) + 1;            // causal prune
    __syncthreads();

    for (int kt = 0; kt < ntiles; ++kt) {
        const int k0 = kt << 6;
        {   // K,V tiles -> tf32 bits
            const float* skp = gK + base + (size_t)(k0 + lr) * rs + lc0;
            const float* svp = gV + base + (size_t)(k0 + lr) * rs + lc0;
            unsigned* kd = (unsigned*)&Ks[lr * ATQ + lc0];
            unsigned* vd = (unsigned*)&Vs[lr * ATV + lc0];
            #pragma unroll
            for (int i = 0; i < 4; ++i) {
                float4 kv = *(const float4*)(skp + i * 4);
                kd[i * 4 + 0] = f2tf(kv.x); kd[i * 4 + 1] = f2tf(kv.y);
                kd[i * 4 + 2] = f2tf(kv.z); kd[i * 4 + 3] = f2tf(kv.w);
                float4 vv = *(const float4*)(svp + i * 4);
                vd[i * 4 + 0] = f2tf(vv.x); vd[i * 4 + 1] = f2tf(vv.y);
                vd[i * 4 + 2] = f2tf(vv.z); vd[i * 4 + 3] = f2tf(vv.w);
            }
        }
        __syncthreads();

        // S = Q @ K^T via mma
        float accs[4][4] = {};
        {
            const unsigned* qsm = (const unsigned*)Qs;
            const unsigned* ksm = (const unsigned*)Ks;
            #pragma unroll
            for (int ksx = 0; ksx < 8; ++ksx) {
                const int kk = ksx * 8;
                unsigned a0 = qsm[(wq * 16 + gid) * ATQ + kk + tig];
                unsigned a1 = qsm[(wq * 16 + 8 + gid) * ATQ + kk + tig];
                unsigned a2 = qsm[(wq * 16 + gid) * ATQ + kk + tig + 4];
                unsigned a3 = qsm[(wq * 16 + 8 + gid) * ATQ + kk + tig + 4];
                #pragma unroll
                for (int nf = 0; nf < 4; ++nf) {
                    unsigned b0 = ksm[(wh * 32 + nf * 8 + gid) * ATQ + kk + tig];
                    unsigned b1 = ksm[(wh * 32 + nf * 8 + gid) * ATQ + kk + tig + 4];
                    mma_tf32(accs[nf], a0, a1, a2, a3, b0, b1);
                }
            }
        }
        // fragment -> Ps with causal mask (scale already folded into Q)
        {
            const int r0 = wq * 16 + gid;
            const int qg0 = q0 + r0, qg1 = qg0 + 8;
            #pragma unroll
            for (int nf = 0; nf < 4; ++nf) {
                int c  = wh * 32 + nf * 8 + tig * 2;
                int kg = k0 + c;
                float2 v0, v1;
                v0.x = (kg     > qg0) ? -1e30f : accs[nf][0];
                v0.y = (kg + 1 > qg0) ? -1e30f : accs[nf][1];
                v1.x = (kg     > qg1) ? -1e30f : accs[nf][2];
                v1.y = (kg + 1 > qg1) ? -1e30f : accs[nf][3];
                *(float2*)&Ps[r0 * ATQ + c]       = v0;
                *(float2*)&Ps[(r0 + 8) * ATQ + c] = v1;
            }
        }
        __syncthreads();

        // online softmax (4 threads/row); stores P as tf32 bits
        {
            const int sub = t & 3;
            float mx = -1e30f;
            #pragma unroll
            for (int c = 0; c < 16; ++c)
                mx = fmaxf(mx, Ps[lr * ATQ + lc0 + c]);
            mx = fmaxf(mx, __shfl_xor_sync(0xffffffffu, mx, 1));
            mx = fmaxf(mx, __shfl_xor_sync(0xffffffffu, mx, 2));
            float m_old = sm_m[lr];
            float m_new = fmaxf(m_old, mx);
            float sum = 0.f;
            #pragma unroll
            for (int c = 0; c < 16; ++c) {
                float p = __expf(Ps[lr * ATQ + lc0 + c] - m_new);
                sum += p;
                ((unsigned*)Ps)[lr * ATQ + lc0 + c] = f2tf(p);
            }
            sum += __shfl_xor_sync(0xffffffffu, sum, 1);
            sum += __shfl_xor_sync(0xffffffffu, sum, 2);
            if (sub == 0) {
                float corr = __expf(m_old - m_new);
                sm_scale[lr] = corr;
                sm_l[lr] = sm_l[lr] * corr + sum;
                sm_m[lr] = m_new;
            }
        }
        __syncthreads();

        // O = O*corr + P @ V via mma
        {
            const float c0 = sm_scale[wq * 16 + gid];
            const float c1 = sm_scale[wq * 16 + 8 + gid];
            #pragma unroll
            for (int nf = 0; nf < 4; ++nf) {
                acco[nf][0] *= c0; acco[nf][1] *= c0;
                acco[nf][2] *= c1; acco[nf][3] *= c1;
            }
            const unsigned* psm = (const unsigned*)Ps;
            const unsigned* vsm = (const unsigned*)Vs;
            #pragma unroll
            for (int ksx = 0; ksx < 8; ++ksx) {
                const int kk = ksx * 8;
                unsigned a0 = psm[(wq * 16 + gid) * ATQ + kk + tig];
                unsigned a1 = psm[(wq * 16 + 8 + gid) * ATQ + kk + tig];
                unsigned a2 = psm[(wq * 16 + gid) * ATQ + kk + tig + 4];
                unsigned a3 = psm[(wq * 16 + 8 + gid) * ATQ + kk + tig + 4];
                #pragma unroll
                for (int nf = 0; nf < 4; ++nf) {
                    unsigned b0 = vsm[(kk + tig) * ATV + wh * 32 + nf * 8 + gid];
                    unsigned b1 = vsm[(kk + tig + 4) * ATV + wh * 32 + nf * 8 + gid];
                    mma_tf32(acco[nf], a0, a1, a2, a3, b0, b1);
                }
            }
        }
        __syncthreads();
    }

    // normalize + store
    {
        const int r0 = wq * 16 + gid;
        const float inv0 = 1.f / sm_l[r0];
        const float inv1 = 1.f / sm_l[r0 + 8];
        #pragma unroll
        for (int nf = 0; nf < 4; ++nf) {
            int c = wh * 32 + nf * 8 + tig * 2;
            float2 v0 = make_float2(acco[nf][0] * inv0, acco[nf][1] * inv0);
            float2 v1 = make_float2(acco[nf][2] * inv1, acco[nf][3] * inv1);
            *(float2*)(gZ + base + (size_t)(q0 + r0) * rs + c)     = v0;
            *(float2*)(gZ + base + (size_t)(q0 + r0 + 8) * rs + c) = v1;
        }
    }
}

// ============================================================================
extern "C" void kernel_launch(void* const* d_in, const int* in_sizes, int n_in,
                              void* d_out, int out_size)
{
    (void)in_sizes; (void)n_in; (void)out_size;
    const float* x  = (const float*)d_in[0];
    const float* WQ = (const float*)d_in[1];
    const float* bQ = (const float*)d_in[2];
    const float* WK = (const float*)d_in[3];
    const float* bK = (const float*)d_in[4];
    const float* WV = (const float*)d_in[5];
    const float* bV = (const float*)d_in[6];
    const float* WO = (const float*)d_in[7];
    const float* bO = (const float*)d_in[8];
    float* out = (float*)d_out;

    float *pQ, *pK, *pV, *pZ;
    cudaGetSymbolAddress((void**)&pQ, g_Q);
    cudaGetSymbolAddress((void**)&pK, g_K);
    cudaGetSymbolAddress((void**)&pV, g_V);
    cudaGetSymbolAddress((void**)&pZ, g_Z);

    cudaFuncSetAttribute(tf32_gemm<true>,
                         cudaFuncAttributeMaxDynamicSharedMemorySize, GEMM_SMEM);
    cudaFuncSetAttribute(tf32_gemm<false>,
                         cudaFuncAttributeMaxDynamicSharedMemorySize, GEMM_SMEM);
    cudaFuncSetAttribute(attn_tc_kernel,
                         cudaFuncAttributeMaxDynamicSharedMemorySize, ATT_SMEM);

    dim3 blk(256);
    dim3 gproj((Hz * DHz) / 128, BSz / 128);      // 8 x 64
    tf32_gemm<true><<<gproj, blk, GEMM_SMEM>>>(x, WQ, bQ, pQ, BSz, Hz * DHz, Dz);
    tf32_gemm<true><<<gproj, blk, GEMM_SMEM>>>(x, WK, bK, pK, BSz, Hz * DHz, Dz);
    tf32_gemm<true><<<gproj, blk, GEMM_SMEM>>>(x, WV, bV, pV, BSz, Hz * DHz, Dz);

    attn_tc_kernel<<<dim3(Sz / 64, Bz * Hz), blk, ATT_SMEM>>>(pQ, pK, pV, pZ);

    dim3 gout(Dz / 128, BSz / 128);               // 8 x 64
    tf32_gemm<false><<<gout, blk, GEMM_SMEM>>>(pZ, WO, bO, out, BSz, Dz, Hz * DHz);
}

// round 12
// speedup vs baseline: 2.9299x; 1.2785x over previous
#include <cuda_runtime.h>
#include <cuda_fp16.h>
#include <math.h>

#define Bz  4
#define Sz  2048
#define Dz  1024
#define Hz  16
#define DHz 64
#define BSz (Bz*Sz)          /* 8192 rows */

// ---- scratch (no allocation allowed; __device__ globals) ----
__device__ __half g_Q[(size_t)BSz * Hz * DHz];
__device__ __half g_K[(size_t)BSz * Hz * DHz];
__device__ __half g_V[(size_t)BSz * Hz * DHz];
__device__ float  g_Z[(size_t)BSz * Hz * DHz];

__device__ __forceinline__ unsigned f2tf(float f) {
    unsigned u;
    asm("cvt.rna.tf32.f32 %0, %1;" : "=r"(u) : "f"(f));
    return u;
}

__device__ __forceinline__ void mma_tf32(float* c,
    unsigned a0, unsigned a1, unsigned a2, unsigned a3,
    unsigned b0, unsigned b1)
{
    asm volatile(
        "mma.sync.aligned.m16n8k8.row.col.f32.tf32.tf32.f32 "
        "{%0,%1,%2,%3}, {%4,%5,%6,%7}, {%8,%9}, {%0,%1,%2,%3};\n"
        : "+f"(c[0]), "+f"(c[1]), "+f"(c[2]), "+f"(c[3])
        : "r"(a0), "r"(a1), "r"(a2), "r"(a3), "r"(b0), "r"(b1));
}

__device__ __forceinline__ void mma_f16(float* c,
    unsigned a0, unsigned a1, unsigned a2, unsigned a3,
    unsigned b0, unsigned b1)
{
    asm volatile(
        "mma.sync.aligned.m16n8k16.row.col.f32.f16.f16.f32 "
        "{%0,%1,%2,%3}, {%4,%5,%6,%7}, {%8,%9}, {%0,%1,%2,%3};\n"
        : "+f"(c[0]), "+f"(c[1]), "+f"(c[2]), "+f"(c[3])
        : "r"(a0), "r"(a1), "r"(a2), "r"(a3), "r"(b0), "r"(b1));
}

__device__ __forceinline__ void ldsm_x4(unsigned& r0, unsigned& r1,
                                        unsigned& r2, unsigned& r3, unsigned a)
{
    asm volatile("ldmatrix.sync.aligned.m8n8.x4.shared.b16 {%0,%1,%2,%3}, [%4];"
                 : "=r"(r0), "=r"(r1), "=r"(r2), "=r"(r3) : "r"(a));
}
__device__ __forceinline__ void ldsm_x4t(unsigned& r0, unsigned& r1,
                                         unsigned& r2, unsigned& r3, unsigned a)
{
    asm volatile("ldmatrix.sync.aligned.m8n8.x4.trans.shared.b16 {%0,%1,%2,%3}, [%4];"
                 : "=r"(r0), "=r"(r1), "=r"(r2), "=r"(r3) : "r"(a));
}

// ============================================================================
// TF32 tensor-core GEMM (validated R6). OT=half writes half output (Q/K/V).
// ============================================================================
#define AP 36
#define BP 136
#define ASZ (128 * AP)
#define BSZ (32 * BP)
#define GEMM_SMEM ((ASZ + BSZ) * 2 * 4)

template <bool PROJ, typename OT>
__global__ __launch_bounds__(256) void tf32_gemm(
    const float* __restrict__ A, const float* __restrict__ Bm,
    const float* __restrict__ bias, OT* __restrict__ C,
    int M, int N, int K)
{
    extern __shared__ float smx[];
    float* Asb[2] = { smx, smx + ASZ };
    float* Bsb[2] = { smx + 2 * ASZ, smx + 2 * ASZ + BSZ };

    const int t    = threadIdx.x;
    const int warp = t >> 5, lane = t & 31;
    const int gid  = lane >> 2, tig = lane & 3;
    const int wm   = warp >> 2, wn = warp & 3;
    const int m0   = blockIdx.y * 128, n0 = blockIdx.x * 128;
    const int lr   = t >> 3, lc = (t & 7) * 4;

    float acc[4][4][4] = {};
    const int NT = K / 32;

    for (int tile = 0; tile <= NT; ++tile) {
        if (tile < NT) {
            const int k0 = tile * 32;
            const int buf = tile & 1;
            float* ad = Asb[buf];
            #pragma unroll
            for (int i = 0; i < 4; ++i) {
                int r = lr + 32 * i;
                unsigned s = (unsigned)__cvta_generic_to_shared(ad + r * AP + lc);
                const float* g = A + (size_t)(m0 + r) * K + k0 + lc;
                asm volatile("cp.async.ca.shared.global [%0], [%1], 16;\n"
                             :: "r"(s), "l"(g));
            }
            float* bd = Bsb[buf];
            #pragma unroll
            for (int i = 0; i < 4; ++i) {
                int n = lc + 32 * i;
                unsigned s = (unsigned)__cvta_generic_to_shared(bd + lr * BP + n);
                const float* g;
                if (PROJ) {
                    int ng = n0 + n;
                    g = Bm + (size_t)(ng >> 6) * ((size_t)K * 64)
                           + (size_t)(k0 + lr) * 64 + (ng & 63);
                } else {
                    g = Bm + (size_t)(k0 + lr) * N + n0 + n;
                }
                asm volatile("cp.async.ca.shared.global [%0], [%1], 16;\n"
                             :: "r"(s), "l"(g));
            }
            asm volatile("cp.async.commit_group;\n");
        }
        if (tile == 0) continue;
        if (tile < NT) asm volatile("cp.async.wait_group 1;\n");
        else           asm volatile("cp.async.wait_group 0;\n");
        __syncthreads();

        const int buf = (tile - 1) & 1;
        const float* as = Asb[buf];
        const float* bs = Bsb[buf];
        #pragma unroll
        for (int ks = 0; ks < 4; ++ks) {
            const int kk = ks * 8;
            unsigned af[4][4];
            #pragma unroll
            for (int mf = 0; mf < 4; ++mf) {
                const float* ap = as + (wm * 64 + mf * 16 + gid) * AP + kk + tig;
                af[mf][0] = f2tf(ap[0]);
                af[mf][1] = f2tf(ap[8 * AP]);
                af[mf][2] = f2tf(ap[4]);
                af[mf][3] = f2tf(ap[8 * AP + 4]);
            }
            unsigned bf[4][2];
            #pragma unroll
            for (int nf = 0; nf < 4; ++nf) {
                const float* bp = bs + (kk + tig) * BP + wn * 32 + nf * 8 + gid;
                bf[nf][0] = f2tf(bp[0]);
                bf[nf][1] = f2tf(bp[4 * BP]);
            }
            #pragma unroll
            for (int mf = 0; mf < 4; ++mf)
                #pragma unroll
                for (int nf = 0; nf < 4; ++nf)
                    mma_tf32(acc[mf][nf], af[mf][0], af[mf][1], af[mf][2],
                             af[mf][3], bf[nf][0], bf[nf][1]);
        }
        __syncthreads();
    }

    #pragma unroll
    for (int mf = 0; mf < 4; ++mf) {
        int r0 = m0 + wm * 64 + mf * 16 + gid;
        #pragma unroll
        for (int nf = 0; nf < 4; ++nf) {
            int c = n0 + wn * 32 + nf * 8 + tig * 2;
            float b0v = bias[c], b1v = bias[c + 1];
            if constexpr (sizeof(OT) == 2) {
                *(__half2*)(C + (size_t)r0 * N + c) =
                    __floats2half2_rn(acc[mf][nf][0] + b0v, acc[mf][nf][1] + b1v);
                *(__half2*)(C + (size_t)(r0 + 8) * N + c) =
                    __floats2half2_rn(acc[mf][nf][2] + b0v, acc[mf][nf][3] + b1v);
            } else {
                float2 v0 = make_float2(acc[mf][nf][0] + b0v, acc[mf][nf][1] + b1v);
                float2 v1 = make_float2(acc[mf][nf][2] + b0v, acc[mf][nf][3] + b1v);
                *(float2*)(C + (size_t)r0 * N + c)       = v0;
                *(float2*)(C + (size_t)(r0 + 8) * N + c) = v1;
            }
        }
    }
}

// ============================================================================
// Causal flash attention, fp16 mma (m16n8k16) + ldmatrix, fp32 softmax.
// CTA = 64 q-rows of one (b,h). 8 warps: wq=warp>>1 (16 q), wh=warp&1.
// Half tiles pitch 72 (144B = 9x16B -> ldmatrix conflict-free).
// Scale 1/8 folded at S fragment->Ps store. Softmax path identical to R10.
// ============================================================================
#define TP  72
#define PSP 68
#define ATT_SMEM (64 * TP * 2 * 4 + (64 * PSP + 3 * 64) * 4)   /* 55040 B */

__global__ __launch_bounds__(256) void attn_f16_kernel(
    const __half* __restrict__ gQ, const __half* __restrict__ gK,
    const __half* __restrict__ gV, float* __restrict__ gZ)
{
    extern __shared__ char smraw[];
    __half* Qh = (__half*)smraw;            // [64][TP]
    __half* Kh = Qh + 64 * TP;
    __half* Vh = Kh + 64 * TP;
    __half* Ph = Vh + 64 * TP;              // probs (half) for PV ldmatrix
    float*  Ps = (float*)(Ph + 64 * TP);    // [64][PSP] fp32 scores
    float* sm_m     = Ps + 64 * PSP;
    float* sm_l     = sm_m + 64;
    float* sm_scale = sm_l + 64;

    const int t    = threadIdx.x;
    const int warp = t >> 5, lane = t & 31;
    const int gid  = lane >> 2, tig = lane & 3;
    const int wq   = warp >> 1, wh = warp & 1;
    const int q0   = blockIdx.x * 64;
    const int b    = blockIdx.y >> 4;
    const int h    = blockIdx.y & 15;
    const size_t base = (size_t)b * Sz * Hz * DHz + (size_t)h * DHz;
    const int rs   = Hz * DHz;              // 1024
    const int lr   = t >> 2, lc0 = (t & 3) * 16;
    const int m0w  = wq * 16;

    const unsigned qb = (unsigned)__cvta_generic_to_shared(Qh);
    const unsigned kb = (unsigned)__cvta_generic_to_shared(Kh);
    const unsigned vb = (unsigned)__cvta_generic_to_shared(Vh);
    const unsigned pb = (unsigned)__cvta_generic_to_shared(Ph);

    if (t < 64) { sm_m[t] = -1e30f; sm_l[t] = 0.f; }

    {   // Q tile (half, 2x 16B per thread)
        const __half* src = gQ + base + (size_t)(q0 + lr) * rs + lc0;
        unsigned d = qb + (unsigned)(lr * TP + lc0) * 2;
        asm volatile("cp.async.ca.shared.global [%0], [%1], 16;\n" :: "r"(d), "l"(src));
        asm volatile("cp.async.ca.shared.global [%0], [%1], 16;\n" :: "r"(d + 16), "l"(src + 8));
    }
    float acco[4][4] = {};
    const int ntiles = (q0 >> 6) + 1;       // causal prune

    // ldmatrix lane address components
    const int a_row = (lane & 7) + ((lane >> 3) & 1) * 8;   // + m0w, + col sel
    const int a_csel = (lane >> 4) << 3;
    const int b_row = (lane & 7) + ((lane >> 4) & 1) * 8;   // B (K): rows keys
    const int b_csel = ((lane >> 3) & 1) << 3;

    for (int kt = 0; kt < ntiles; ++kt) {
        const int k0 = kt << 6;
        {   // K, V tiles
            const __half* sk = gK + base + (size_t)(k0 + lr) * rs + lc0;
            const __half* sv = gV + base + (size_t)(k0 + lr) * rs + lc0;
            unsigned dk = kb + (unsigned)(lr * TP + lc0) * 2;
            unsigned dv = vb + (unsigned)(lr * TP + lc0) * 2;
            asm volatile("cp.async.ca.shared.global [%0], [%1], 16;\n" :: "r"(dk), "l"(sk));
            asm volatile("cp.async.ca.shared.global [%0], [%1], 16;\n" :: "r"(dk + 16), "l"(sk + 8));
            asm volatile("cp.async.ca.shared.global [%0], [%1], 16;\n" :: "r"(dv), "l"(sv));
            asm volatile("cp.async.ca.shared.global [%0], [%1], 16;\n" :: "r"(dv + 16), "l"(sv + 8));
        }
        asm volatile("cp.async.commit_group;\n");
        asm volatile("cp.async.wait_group 0;\n");
        __syncthreads();

        // ---- S = Q @ K^T (fp16 mma, k=64 in 4 steps) ----
        float accs[4][4] = {};
        #pragma unroll
        for (int ks = 0; ks < 4; ++ks) {
            const int kk = ks * 16;
            unsigned a0, a1, a2, a3;
            ldsm_x4(a0, a1, a2, a3,
                    qb + (unsigned)((m0w + a_row) * TP + kk + a_csel) * 2);
            #pragma unroll
            for (int pr = 0; pr < 2; ++pr) {
                const int nn = wh * 32 + pr * 16;
                unsigned b0, b1, b2, b3;
                ldsm_x4(b0, b1, b2, b3,
                        kb + (unsigned)((nn + b_row) * TP + kk + b_csel) * 2);
                mma_f16(accs[pr * 2],     a0, a1, a2, a3, b0, b1);
                mma_f16(accs[pr * 2 + 1], a0, a1, a2, a3, b2, b3);
            }
        }
        // fragment -> Ps with scale (1/8) + causal mask
        {
            const int r0 = m0w + gid;
            const int qg0 = q0 + r0, qg1 = qg0 + 8;
            #pragma unroll
            for (int nf = 0; nf < 4; ++nf) {
                int c  = wh * 32 + nf * 8 + tig * 2;
                int kg = k0 + c;
                float2 v0, v1;
                v0.x = (kg     > qg0) ? -1e30f : accs[nf][0] * 0.125f;
                v0.y = (kg + 1 > qg0) ? -1e30f : accs[nf][1] * 0.125f;
                v1.x = (kg     > qg1) ? -1e30f : accs[nf][2] * 0.125f;
                v1.y = (kg + 1 > qg1) ? -1e30f : accs[nf][3] * 0.125f;
                *(float2*)&Ps[r0 * PSP + c]       = v0;
                *(float2*)&Ps[(r0 + 8) * PSP + c] = v1;
            }
        }
        __syncthreads();

        // ---- online softmax (4 threads/row); writes P as half2 ----
        {
            const int sub = t & 3;
            float mx = -1e30f;
            #pragma unroll
            for (int c = 0; c < 16; ++c)
                mx = fmaxf(mx, Ps[lr * PSP + lc0 + c]);
            mx = fmaxf(mx, __shfl_xor_sync(0xffffffffu, mx, 1));
            mx = fmaxf(mx, __shfl_xor_sync(0xffffffffu, mx, 2));
            float m_old = sm_m[lr];
            float m_new = fmaxf(m_old, mx);
            float sum = 0.f;
            #pragma unroll
            for (int c = 0; c < 16; c += 2) {
                float p0 = __expf(Ps[lr * PSP + lc0 + c]     - m_new);
                float p1 = __expf(Ps[lr * PSP + lc0 + c + 1] - m_new);
                sum += p0 + p1;
                *(__half2*)&Ph[lr * TP + lc0 + c] = __floats2half2_rn(p0, p1);
            }
            sum += __shfl_xor_sync(0xffffffffu, sum, 1);
            sum += __shfl_xor_sync(0xffffffffu, sum, 2);
            if (sub == 0) {
                float corr = __expf(m_old - m_new);
                sm_scale[lr] = corr;
                sm_l[lr] = sm_l[lr] * corr + sum;
                sm_m[lr] = m_new;
            }
        }
        __syncthreads();

        // ---- O = O*corr + P @ V (fp16 mma; V via ldmatrix.trans) ----
        {
            const float c0 = sm_scale[m0w + gid];
            const float c1 = sm_scale[m0w + 8 + gid];
            #pragma unroll
            for (int nf = 0; nf < 4; ++nf) {
                acco[nf][0] *= c0; acco[nf][1] *= c0;
                acco[nf][2] *= c1; acco[nf][3] *= c1;
            }
            #pragma unroll
            for (int ks = 0; ks < 4; ++ks) {
                const int kk = ks * 16;
                unsigned a0, a1, a2, a3;
                ldsm_x4(a0, a1, a2, a3,
                        pb + (unsigned)((m0w + a_row) * TP + kk + a_csel) * 2);
                #pragma unroll
                for (int pr = 0; pr < 2; ++pr) {
                    const int nn = wh * 32 + pr * 16;
                    // trans: rows = keys (kk block), cols = dh (nn block)
                    int vrow = kk + (lane & 7) + ((lane >> 3) & 1) * 8;
                    int vcol = nn + (((lane >> 4) & 1) << 3);
                    unsigned b0, b1, b2, b3;
                    ldsm_x4t(b0, b1, b2, b3,
                             vb + (unsigned)(vrow * TP + vcol) * 2);
                    mma_f16(acco[pr * 2],     a0, a1, a2, a3, b0, b1);
                    mma_f16(acco[pr * 2 + 1], a0, a1, a2, a3, b2, b3);
                }
            }
        }
        __syncthreads();
    }

    // normalize + store
    {
        const int r0 = m0w + gid;
        const float inv0 = 1.f / sm_l[r0];
        const float inv1 = 1.f / sm_l[r0 + 8];
        #pragma unroll
        for (int nf = 0; nf < 4; ++nf) {
            int c = wh * 32 + nf * 8 + tig * 2;
            float2 v0 = make_float2(acco[nf][0] * inv0, acco[nf][1] * inv0);
            float2 v1 = make_float2(acco[nf][2] * inv1, acco[nf][3] * inv1);
            *(float2*)(gZ + base + (size_t)(q0 + r0) * rs + c)     = v0;
            *(float2*)(gZ + base + (size_t)(q0 + r0 + 8) * rs + c) = v1;
        }
    }
}

// ============================================================================
extern "C" void kernel_launch(void* const* d_in, const int* in_sizes, int n_in,
                              void* d_out, int out_size)
{
    (void)in_sizes; (void)n_in; (void)out_size;
    const float* x  = (const float*)d_in[0];
    const float* WQ = (const float*)d_in[1];
    const float* bQ = (const float*)d_in[2];
    const float* WK = (const float*)d_in[3];
    const float* bK = (const float*)d_in[4];
    const float* WV = (const float*)d_in[5];
    const float* bV = (const float*)d_in[6];
    const float* WO = (const float*)d_in[7];
    const float* bO = (const float*)d_in[8];
    float* out = (float*)d_out;

    __half *pQ, *pK, *pV; float *pZ;
    cudaGetSymbolAddress((void**)&pQ, g_Q);
    cudaGetSymbolAddress((void**)&pK, g_K);
    cudaGetSymbolAddress((void**)&pV, g_V);
    cudaGetSymbolAddress((void**)&pZ, g_Z);

    cudaFuncSetAttribute((const void*)tf32_gemm<true, __half>,
                         cudaFuncAttributeMaxDynamicSharedMemorySize, GEMM_SMEM);
    cudaFuncSetAttribute((const void*)tf32_gemm<false, float>,
                         cudaFuncAttributeMaxDynamicSharedMemorySize, GEMM_SMEM);
    cudaFuncSetAttribute((const void*)attn_f16_kernel,
                         cudaFuncAttributeMaxDynamicSharedMemorySize, ATT_SMEM);

    dim3 blk(256);
    dim3 gproj((Hz * DHz) / 128, BSz / 128);      // 8 x 64
    tf32_gemm<true, __half><<<gproj, blk, GEMM_SMEM>>>(x, WQ, bQ, pQ, BSz, Hz * DHz, Dz);
    tf32_gemm<true, __half><<<gproj, blk, GEMM_SMEM>>>(x, WK, bK, pK, BSz, Hz * DHz, Dz);
    tf32_gemm<true, __half><<<gproj, blk, GEMM_SMEM>>>(x, WV, bV, pV, BSz, Hz * DHz, Dz);

    attn_f16_kernel<<<dim3(Sz / 64, Bz * Hz), blk, ATT_SMEM>>>(pQ, pK, pV, pZ);

    dim3 gout(Dz / 128, BSz / 128);               // 8 x 64
    tf32_gemm<false, float><<<gout, blk, GEMM_SMEM>>>(pZ, WO, bO, out, BSz, Dz, Hz * DHz);
}

// round 13
// speedup vs baseline: 4.6868x; 1.5997x over previous
#include <cuda_runtime.h>
#include <cuda_fp16.h>
#include <math.h>

#define Bz  4
#define Sz  2048
#define Dz  1024
#define Hz  16
#define DHz 64
#define BSz (Bz*Sz)          /* 8192 rows */

// ---- scratch (no allocation allowed; __device__ globals) ----
__device__ __half g_Xh[(size_t)BSz * Dz];
__device__ __half g_Wq[(size_t)Dz * Hz * DHz];
__device__ __half g_Wk[(size_t)Dz * Hz * DHz];
__device__ __half g_Wv[(size_t)Dz * Hz * DHz];
__device__ __half g_Wo[(size_t)Hz * DHz * Dz];
__device__ __half g_Q[(size_t)BSz * Hz * DHz];
__device__ __half g_K[(size_t)BSz * Hz * DHz];
__device__ __half g_V[(size_t)BSz * Hz * DHz];
__device__ __half g_Zh[(size_t)BSz * Hz * DHz];

__device__ __forceinline__ void mma_f16(float* c,
    unsigned a0, unsigned a1, unsigned a2, unsigned a3,
    unsigned b0, unsigned b1)
{
    asm volatile(
        "mma.sync.aligned.m16n8k16.row.col.f32.f16.f16.f32 "
        "{%0,%1,%2,%3}, {%4,%5,%6,%7}, {%8,%9}, {%0,%1,%2,%3};\n"
        : "+f"(c[0]), "+f"(c[1]), "+f"(c[2]), "+f"(c[3])
        : "r"(a0), "r"(a1), "r"(a2), "r"(a3), "r"(b0), "r"(b1));
}

__device__ __forceinline__ void ldsm_x4(unsigned& r0, unsigned& r1,
                                        unsigned& r2, unsigned& r3, unsigned a)
{
    asm volatile("ldmatrix.sync.aligned.m8n8.x4.shared.b16 {%0,%1,%2,%3}, [%4];"
                 : "=r"(r0), "=r"(r1), "=r"(r2), "=r"(r3) : "r"(a));
}
__device__ __forceinline__ void ldsm_x4t(unsigned& r0, unsigned& r1,
                                         unsigned& r2, unsigned& r3, unsigned a)
{
    asm volatile("ldmatrix.sync.aligned.m8n8.x4.trans.shared.b16 {%0,%1,%2,%3}, [%4];"
                 : "=r"(r0), "=r"(r1), "=r"(r2), "=r"(r3) : "r"(a));
}

// ============================================================================
// Conversion kernels (one-shot, ~15us total)
// ============================================================================
__global__ void cvt_f2h(const float* __restrict__ s, __half* __restrict__ d, int n)
{
    int i = (blockIdx.x * blockDim.x + threadIdx.x) * 4;
    if (i < n) {
        float4 v = *(const float4*)(s + i);
        *(__half2*)(d + i)     = __floats2half2_rn(v.x, v.y);
        *(__half2*)(d + i + 2) = __floats2half2_rn(v.z, v.w);
    }
}

// W (H, D, DH) -> row-major Bh[k][n], n = h*64+e : Bh[k*1024+n] = W[h][k][e]
__global__ void cvt_w_proj(const float* __restrict__ W, __half* __restrict__ Bh)
{
    int idx = blockIdx.x * blockDim.x + threadIdx.x;   // 262144
    int k = idx >> 8;
    int n = (idx & 255) * 4;
    const float* src = W + ((size_t)(n >> 6) << 16) + k * 64 + (n & 63);
    float4 v = *(const float4*)src;
    *(__half2*)(Bh + (size_t)k * 1024 + n)     = __floats2half2_rn(v.x, v.y);
    *(__half2*)(Bh + (size_t)k * 1024 + n + 2) = __floats2half2_rn(v.z, v.w);
}

// ============================================================================
// FP16 tensor-core GEMM: C[M,N] = A[M,K] @ B[K,N] + bias[N]
// A, B half row-major. 128x128 tile, BK=32, 256 thr (8 warps 2x4, 64x32 each),
// mma.m16n8k16 + ldmatrix (A) / ldmatrix.trans (B), cp.async double buffer.
// Pitches: A 40 halves (80B: 5x16B, coprime 8 -> ldsm conflict-free),
//          B 136 halves (272B: 17x16B -> conflict-free).
// ============================================================================
#define HAP 40
#define HBP 136
#define HASZ (128 * HAP)
#define HBSZ (32 * HBP)
#define HGEMM_SMEM ((HASZ + HBSZ) * 2 * 2)   /* 37888 B */

template <typename OT>
__global__ __launch_bounds__(256) void f16_gemm(
    const __half* __restrict__ A, const __half* __restrict__ Bm,
    const float* __restrict__ bias, OT* __restrict__ C,
    int M, int N, int K)
{
    extern __shared__ __half smh[];
    __half* Asb[2] = { smh, smh + HASZ };
    __half* Bsb[2] = { smh + 2 * HASZ, smh + 2 * HASZ + HBSZ };

    const int t    = threadIdx.x;
    const int warp = t >> 5, lane = t & 31;
    const int gid  = lane >> 2, tig = lane & 3;
    const int wm   = warp >> 2, wn = warp & 3;
    const int m0   = blockIdx.y * 128, n0 = blockIdx.x * 128;

    // ldmatrix lane address components (validated in R12 attention kernel)
    const int a_row  = (lane & 7) + ((lane >> 3) & 1) * 8;
    const int a_csel = ((lane >> 4) & 1) * 8;

    float acc[4][4][4] = {};
    const int NT = K / 32;

    for (int tile = 0; tile <= NT; ++tile) {
        if (tile < NT) {
            const int k0 = tile * 32;
            const int buf = tile & 1;
            __half* ad = Asb[buf];
            __half* bd = Bsb[buf];
            #pragma unroll
            for (int i = 0; i < 2; ++i) {       // A: 512 16B-chunks / 256 thr
                int c = t + i * 256;
                int r = c >> 2, col = (c & 3) * 8;
                unsigned s = (unsigned)__cvta_generic_to_shared(ad + r * HAP + col);
                const __half* g = A + (size_t)(m0 + r) * K + k0 + col;
                asm volatile("cp.async.ca.shared.global [%0], [%1], 16;\n"
                             :: "r"(s), "l"(g));
            }
            #pragma unroll
            for (int i = 0; i < 2; ++i) {       // B: 512 chunks
                int c = t + i * 256;
                int r = c >> 4, col = (c & 15) * 8;
                unsigned s = (unsigned)__cvta_generic_to_shared(bd + r * HBP + col);
                const __half* g = Bm + (size_t)(k0 + r) * N + n0 + col;
                asm volatile("cp.async.ca.shared.global [%0], [%1], 16;\n"
                             :: "r"(s), "l"(g));
            }
            asm volatile("cp.async.commit_group;\n");
        }
        if (tile == 0) continue;
        if (tile < NT) asm volatile("cp.async.wait_group 1;\n");
        else           asm volatile("cp.async.wait_group 0;\n");
        __syncthreads();

        const int buf = (tile - 1) & 1;
        const unsigned ab = (unsigned)__cvta_generic_to_shared(Asb[buf]);
        const unsigned bb = (unsigned)__cvta_generic_to_shared(Bsb[buf]);
        #pragma unroll
        for (int ks = 0; ks < 2; ++ks) {
            const int kk = ks * 16;
            unsigned af[4][4];
            #pragma unroll
            for (int mf = 0; mf < 4; ++mf)
                ldsm_x4(af[mf][0], af[mf][1], af[mf][2], af[mf][3],
                        ab + (unsigned)((wm * 64 + mf * 16 + a_row) * HAP
                                        + kk + a_csel) * 2);
            #pragma unroll
            for (int pr = 0; pr < 2; ++pr) {
                const int nn = wn * 32 + pr * 16;
                unsigned b0, b1, b2, b3;
                ldsm_x4t(b0, b1, b2, b3,
                         bb + (unsigned)((kk + a_row) * HBP + nn + a_csel) * 2);
                #pragma unroll
                for (int mf = 0; mf < 4; ++mf) {
                    mma_f16(acc[mf][pr * 2],     af[mf][0], af[mf][1],
                            af[mf][2], af[mf][3], b0, b1);
                    mma_f16(acc[mf][pr * 2 + 1], af[mf][0], af[mf][1],
                            af[mf][2], af[mf][3], b2, b3);
                }
            }
        }
        __syncthreads();
    }

    #pragma unroll
    for (int mf = 0; mf < 4; ++mf) {
        int r0 = m0 + wm * 64 + mf * 16 + gid;
        #pragma unroll
        for (int nf = 0; nf < 4; ++nf) {
            int c = n0 + wn * 32 + nf * 8 + tig * 2;
            float b0v = bias[c], b1v = bias[c + 1];
            if constexpr (sizeof(OT) == 2) {
                *(__half2*)(C + (size_t)r0 * N + c) =
                    __floats2half2_rn(acc[mf][nf][0] + b0v, acc[mf][nf][1] + b1v);
                *(__half2*)(C + (size_t)(r0 + 8) * N + c) =
                    __floats2half2_rn(acc[mf][nf][2] + b0v, acc[mf][nf][3] + b1v);
            } else {
                float2 v0 = make_float2(acc[mf][nf][0] + b0v, acc[mf][nf][1] + b1v);
                float2 v1 = make_float2(acc[mf][nf][2] + b0v, acc[mf][nf][3] + b1v);
                *(float2*)(C + (size_t)r0 * N + c)       = v0;
                *(float2*)(C + (size_t)(r0 + 8) * N + c) = v1;
            }
        }
    }
}

// ============================================================================
// Causal flash attention, fp16 mma + ldmatrix, fp32 softmax (validated R12).
// Only change: Z written as half for the fp16 O-projection GEMM.
// ============================================================================
#define TP  72
#define PSP 68
#define ATT_SMEM (64 * TP * 2 * 4 + (64 * PSP + 3 * 64) * 4)   /* 55040 B */

__global__ __launch_bounds__(256) void attn_f16_kernel(
    const __half* __restrict__ gQ, const __half* __restrict__ gK,
    const __half* __restrict__ gV, __half* __restrict__ gZ)
{
    extern __shared__ char smraw[];
    __half* Qh = (__half*)smraw;            // [64][TP]
    __half* Kh = Qh + 64 * TP;
    __half* Vh = Kh + 64 * TP;
    __half* Ph = Vh + 64 * TP;              // probs (half) for PV ldmatrix
    float*  Ps = (float*)(Ph + 64 * TP);    // [64][PSP] fp32 scores
    float* sm_m     = Ps + 64 * PSP;
    float* sm_l     = sm_m + 64;
    float* sm_scale = sm_l + 64;

    const int t    = threadIdx.x;
    const int warp = t >> 5, lane = t & 31;
    const int gid  = lane >> 2, tig = lane & 3;
    const int wq   = warp >> 1, wh = warp & 1;
    const int q0   = blockIdx.x * 64;
    const int b    = blockIdx.y >> 4;
    const int h    = blockIdx.y & 15;
    const size_t base = (size_t)b * Sz * Hz * DHz + (size_t)h * DHz;
    const int rs   = Hz * DHz;              // 1024
    const int lr   = t >> 2, lc0 = (t & 3) * 16;
    const int m0w  = wq * 16;

    const unsigned qb = (unsigned)__cvta_generic_to_shared(Qh);
    const unsigned kb = (unsigned)__cvta_generic_to_shared(Kh);
    const unsigned vb = (unsigned)__cvta_generic_to_shared(Vh);
    const unsigned pb = (unsigned)__cvta_generic_to_shared(Ph);

    if (t < 64) { sm_m[t] = -1e30f; sm_l[t] = 0.f; }

    {   // Q tile
        const __half* src = gQ + base + (size_t)(q0 + lr) * rs + lc0;
        unsigned d = qb + (unsigned)(lr * TP + lc0) * 2;
        asm volatile("cp.async.ca.shared.global [%0], [%1], 16;\n" :: "r"(d), "l"(src));
        asm volatile("cp.async.ca.shared.global [%0], [%1], 16;\n" :: "r"(d + 16), "l"(src + 8));
    }
    float acco[4][4] = {};
    const int ntiles = (q0 >> 6) + 1;       // causal prune

    const int a_row = (lane & 7) + ((lane >> 3) & 1) * 8;
    const int a_csel = (lane >> 4) << 3;
    const int b_row = (lane & 7) + ((lane >> 4) & 1) * 8;
    const int b_csel = ((lane >> 3) & 1) << 3;

    for (int kt = 0; kt < ntiles; ++kt) {
        const int k0 = kt << 6;
        {   // K, V tiles
            const __half* sk = gK + base + (size_t)(k0 + lr) * rs + lc0;
            const __half* sv = gV + base + (size_t)(k0 + lr) * rs + lc0;
            unsigned dk = kb + (unsigned)(lr * TP + lc0) * 2;
            unsigned dv = vb + (unsigned)(lr * TP + lc0) * 2;
            asm volatile("cp.async.ca.shared.global [%0], [%1], 16;\n" :: "r"(dk), "l"(sk));
            asm volatile("cp.async.ca.shared.global [%0], [%1], 16;\n" :: "r"(dk + 16), "l"(sk + 8));
            asm volatile("cp.async.ca.shared.global [%0], [%1], 16;\n" :: "r"(dv), "l"(sv));
            asm volatile("cp.async.ca.shared.global [%0], [%1], 16;\n" :: "r"(dv + 16), "l"(sv + 8));
        }
        asm volatile("cp.async.commit_group;\n");
        asm volatile("cp.async.wait_group 0;\n");
        __syncthreads();

        // ---- S = Q @ K^T ----
        float accs[4][4] = {};
        #pragma unroll
        for (int ks = 0; ks < 4; ++ks) {
            const int kk = ks * 16;
            unsigned a0, a1, a2, a3;
            ldsm_x4(a0, a1, a2, a3,
                    qb + (unsigned)((m0w + a_row) * TP + kk + a_csel) * 2);
            #pragma unroll
            for (int pr = 0; pr < 2; ++pr) {
                const int nn = wh * 32 + pr * 16;
                unsigned b0, b1, b2, b3;
                ldsm_x4(b0, b1, b2, b3,
                        kb + (unsigned)((nn + b_row) * TP + kk + b_csel) * 2);
                mma_f16(accs[pr * 2],     a0, a1, a2, a3, b0, b1);
                mma_f16(accs[pr * 2 + 1], a0, a1, a2, a3, b2, b3);
            }
        }
        // fragment -> Ps with scale (1/8) + causal mask
        {
            const int r0 = m0w + gid;
            const int qg0 = q0 + r0, qg1 = qg0 + 8;
            #pragma unroll
            for (int nf = 0; nf < 4; ++nf) {
                int c  = wh * 32 + nf * 8 + tig * 2;
                int kg = k0 + c;
                float2 v0, v1;
                v0.x = (kg     > qg0) ? -1e30f : accs[nf][0] * 0.125f;
                v0.y = (kg + 1 > qg0) ? -1e30f : accs[nf][1] * 0.125f;
                v1.x = (kg     > qg1) ? -1e30f : accs[nf][2] * 0.125f;
                v1.y = (kg + 1 > qg1) ? -1e30f : accs[nf][3] * 0.125f;
                *(float2*)&Ps[r0 * PSP + c]       = v0;
                *(float2*)&Ps[(r0 + 8) * PSP + c] = v1;
            }
        }
        __syncthreads();

        // ---- online softmax ----
        {
            const int sub = t & 3;
            float mx = -1e30f;
            #pragma unroll
            for (int c = 0; c < 16; ++c)
                mx = fmaxf(mx, Ps[lr * PSP + lc0 + c]);
            mx = fmaxf(mx, __shfl_xor_sync(0xffffffffu, mx, 1));
            mx = fmaxf(mx, __shfl_xor_sync(0xffffffffu, mx, 2));
            float m_old = sm_m[lr];
            float m_new = fmaxf(m_old, mx);
            float sum = 0.f;
            #pragma unroll
            for (int c = 0; c < 16; c += 2) {
                float p0 = __expf(Ps[lr * PSP + lc0 + c]     - m_new);
                float p1 = __expf(Ps[lr * PSP + lc0 + c + 1] - m_new);
                sum += p0 + p1;
                *(__half2*)&Ph[lr * TP + lc0 + c] = __floats2half2_rn(p0, p1);
            }
            sum += __shfl_xor_sync(0xffffffffu, sum, 1);
            sum += __shfl_xor_sync(0xffffffffu, sum, 2);
            if (sub == 0) {
                float corr = __expf(m_old - m_new);
                sm_scale[lr] = corr;
                sm_l[lr] = sm_l[lr] * corr + sum;
                sm_m[lr] = m_new;
            }
        }
        __syncthreads();

        // ---- O = O*corr + P @ V ----
        {
            const float c0 = sm_scale[m0w + gid];
            const float c1 = sm_scale[m0w + 8 + gid];
            #pragma unroll
            for (int nf = 0; nf < 4; ++nf) {
                acco[nf][0] *= c0; acco[nf][1] *= c0;
                acco[nf][2] *= c1; acco[nf][3] *= c1;
            }
            #pragma unroll
            for (int ks = 0; ks < 4; ++ks) {
                const int kk = ks * 16;
                unsigned a0, a1, a2, a3;
                ldsm_x4(a0, a1, a2, a3,
                        pb + (unsigned)((m0w + a_row) * TP + kk + a_csel) * 2);
                #pragma unroll
                for (int pr = 0; pr < 2; ++pr) {
                    const int nn = wh * 32 + pr * 16;
                    int vrow = kk + (lane & 7) + ((lane >> 3) & 1) * 8;
                    int vcol = nn + (((lane >> 4) & 1) << 3);
                    unsigned b0, b1, b2, b3;
                    ldsm_x4t(b0, b1, b2, b3,
                             vb + (unsigned)(vrow * TP + vcol) * 2);
                    mma_f16(acco[pr * 2],     a0, a1, a2, a3, b0, b1);
                    mma_f16(acco[pr * 2 + 1], a0, a1, a2, a3, b2, b3);
                }
            }
        }
        __syncthreads();
    }

    // normalize + store (half)
    {
        const int r0 = m0w + gid;
        const float inv0 = 1.f / sm_l[r0];
        const float inv1 = 1.f / sm_l[r0 + 8];
        #pragma unroll
        for (int nf = 0; nf < 4; ++nf) {
            int c = wh * 32 + nf * 8 + tig * 2;
            *(__half2*)(gZ + base + (size_t)(q0 + r0) * rs + c) =
                __floats2half2_rn(acco[nf][0] * inv0, acco[nf][1] * inv0);
            *(__half2*)(gZ + base + (size_t)(q0 + r0 + 8) * rs + c) =
                __floats2half2_rn(acco[nf][2] * inv1, acco[nf][3] * inv1);
        }
    }
}

// ============================================================================
extern "C" void kernel_launch(void* const* d_in, const int* in_sizes, int n_in,
                              void* d_out, int out_size)
{
    (void)in_sizes; (void)n_in; (void)out_size;
    const float* x  = (const float*)d_in[0];
    const float* WQ = (const float*)d_in[1];
    const float* bQ = (const float*)d_in[2];
    const float* WK = (const float*)d_in[3];
    const float* bK = (const float*)d_in[4];
    const float* WV = (const float*)d_in[5];
    const float* bV = (const float*)d_in[6];
    const float* WO = (const float*)d_in[7];
    const float* bO = (const float*)d_in[8];
    float* out = (float*)d_out;

    __half *pXh, *pWq, *pWk, *pWv, *pWo, *pQ, *pK, *pV, *pZ;
    cudaGetSymbolAddress((void**)&pXh, g_Xh);
    cudaGetSymbolAddress((void**)&pWq, g_Wq);
    cudaGetSymbolAddress((void**)&pWk, g_Wk);
    cudaGetSymbolAddress((void**)&pWv, g_Wv);
    cudaGetSymbolAddress((void**)&pWo, g_Wo);
    cudaGetSymbolAddress((void**)&pQ,  g_Q);
    cudaGetSymbolAddress((void**)&pK,  g_K);
    cudaGetSymbolAddress((void**)&pV,  g_V);
    cudaGetSymbolAddress((void**)&pZ,  g_Zh);

    cudaFuncSetAttribute((const void*)f16_gemm<__half>,
                         cudaFuncAttributeMaxDynamicSharedMemorySize, HGEMM_SMEM);
    cudaFuncSetAttribute((const void*)f16_gemm<float>,
                         cudaFuncAttributeMaxDynamicSharedMemorySize, HGEMM_SMEM);
    cudaFuncSetAttribute((const void*)attn_f16_kernel,
                         cudaFuncAttributeMaxDynamicSharedMemorySize, ATT_SMEM);

    // ---- conversions ----
    const int NX = BSz * Dz;                  // 8388608
    cvt_f2h<<<NX / 4 / 256, 256>>>(x, pXh, NX);
    cvt_w_proj<<<1024, 256>>>(WQ, pWq);
    cvt_w_proj<<<1024, 256>>>(WK, pWk);
    cvt_w_proj<<<1024, 256>>>(WV, pWv);
    const int NW = Hz * DHz * Dz;             // 1048576 (W_O already [k][n])
    cvt_f2h<<<NW / 4 / 256, 256>>>(WO, pWo, NW);

    // ---- projections ----
    dim3 blk(256);
    dim3 gproj((Hz * DHz) / 128, BSz / 128);  // 8 x 64
    f16_gemm<__half><<<gproj, blk, HGEMM_SMEM>>>(pXh, pWq, bQ, pQ, BSz, Hz * DHz, Dz);
    f16_gemm<__half><<<gproj, blk, HGEMM_SMEM>>>(pXh, pWk, bK, pK, BSz, Hz * DHz, Dz);
    f16_gemm<__half><<<gproj, blk, HGEMM_SMEM>>>(pXh, pWv, bV, pV, BSz, Hz * DHz, Dz);

    // ---- attention ----
    attn_f16_kernel<<<dim3(Sz / 64, Bz * Hz), blk, ATT_SMEM>>>(pQ, pK, pV, pZ);

    // ---- output projection ----
    dim3 gout(Dz / 128, BSz / 128);           // 8 x 64
    f16_gemm<float><<<gout, blk, HGEMM_SMEM>>>(pZ, pWo, bO, out, BSz, Dz, Hz * DHz);
}

// round 16
// speedup vs baseline: 6.3293x; 1.3504x over previous
#include <cuda_runtime.h>
#include <cuda_fp16.h>
#include <math.h>

#define Bz  4
#define Sz  2048
#define Dz  1024
#define Hz  16
#define DHz 64
#define BSz (Bz*Sz)          /* 8192 rows */

// ---- scratch (no allocation allowed; __device__ globals) ----
__device__ __half g_Xh[(size_t)BSz * Dz];
__device__ __half g_Wq[(size_t)Dz * Hz * DHz];
__device__ __half g_Wk[(size_t)Dz * Hz * DHz];
__device__ __half g_Wv[(size_t)Dz * Hz * DHz];
__device__ __half g_Wo[(size_t)Hz * DHz * Dz];
__device__ __half g_Q[(size_t)BSz * Hz * DHz];
__device__ __half g_K[(size_t)BSz * Hz * DHz];
__device__ __half g_V[(size_t)BSz * Hz * DHz];
__device__ __half g_Zh[(size_t)BSz * Hz * DHz];

__device__ __forceinline__ void mma_f16(float* c,
    unsigned a0, unsigned a1, unsigned a2, unsigned a3,
    unsigned b0, unsigned b1)
{
    asm volatile(
        "mma.sync.aligned.m16n8k16.row.col.f32.f16.f16.f32 "
        "{%0,%1,%2,%3}, {%4,%5,%6,%7}, {%8,%9}, {%0,%1,%2,%3};\n"
        : "+f"(c[0]), "+f"(c[1]), "+f"(c[2]), "+f"(c[3])
        : "r"(a0), "r"(a1), "r"(a2), "r"(a3), "r"(b0), "r"(b1));
}

__device__ __forceinline__ void ldsm_x4(unsigned& r0, unsigned& r1,
                                        unsigned& r2, unsigned& r3, unsigned a)
{
    asm volatile("ldmatrix.sync.aligned.m8n8.x4.shared.b16 {%0,%1,%2,%3}, [%4];"
                 : "=r"(r0), "=r"(r1), "=r"(r2), "=r"(r3) : "r"(a));
}
__device__ __forceinline__ void ldsm_x4t(unsigned& r0, unsigned& r1,
                                         unsigned& r2, unsigned& r3, unsigned a)
{
    asm volatile("ldmatrix.sync.aligned.m8n8.x4.trans.shared.b16 {%0,%1,%2,%3}, [%4];"
                 : "=r"(r0), "=r"(r1), "=r"(r2), "=r"(r3) : "r"(a));
}

// ============================================================================
// Conversion kernels (one-shot, ~15us total)
// ============================================================================
__global__ void cvt_f2h(const float* __restrict__ s, __half* __restrict__ d, int n)
{
    int i = (blockIdx.x * blockDim.x + threadIdx.x) * 4;
    if (i < n) {
        float4 v = *(const float4*)(s + i);
        *(__half2*)(d + i)     = __floats2half2_rn(v.x, v.y);
        *(__half2*)(d + i + 2) = __floats2half2_rn(v.z, v.w);
    }
}

// W (H, D, DH) -> row-major Bh[k][n], n = h*64+e
__global__ void cvt_w_proj(const float* __restrict__ W, __half* __restrict__ Bh)
{
    int idx = blockIdx.x * blockDim.x + threadIdx.x;   // 262144
    int k = idx >> 8;
    int n = (idx & 255) * 4;
    const float* src = W + ((size_t)(n >> 6) << 16) + k * 64 + (n & 63);
    float4 v = *(const float4*)src;
    *(__half2*)(Bh + (size_t)k * 1024 + n)     = __floats2half2_rn(v.x, v.y);
    *(__half2*)(Bh + (size_t)k * 1024 + n + 2) = __floats2half2_rn(v.z, v.w);
}

// ============================================================================
// FP16 tensor-core GEMM (validated R13, unchanged)
// ============================================================================
#define HAP 40
#define HBP 136
#define HASZ (128 * HAP)
#define HBSZ (32 * HBP)
#define HGEMM_SMEM ((HASZ + HBSZ) * 2 * 2)   /* 37888 B */

template <typename OT>
__global__ __launch_bounds__(256) void f16_gemm(
    const __half* __restrict__ A, const __half* __restrict__ Bm,
    const float* __restrict__ bias, OT* __restrict__ C,
    int M, int N, int K)
{
    extern __shared__ __half smh[];
    __half* Asb[2] = { smh, smh + HASZ };
    __half* Bsb[2] = { smh + 2 * HASZ, smh + 2 * HASZ + HBSZ };

    const int t    = threadIdx.x;
    const int warp = t >> 5, lane = t & 31;
    const int gid  = lane >> 2, tig = lane & 3;
    const int wm   = warp >> 2, wn = warp & 3;
    const int m0   = blockIdx.y * 128, n0 = blockIdx.x * 128;

    const int a_row  = (lane & 7) + ((lane >> 3) & 1) * 8;
    const int a_csel = ((lane >> 4) & 1) * 8;

    float acc[4][4][4] = {};
    const int NT = K / 32;

    for (int tile = 0; tile <= NT; ++tile) {
        if (tile < NT) {
            const int k0 = tile * 32;
            const int buf = tile & 1;
            __half* ad = Asb[buf];
            __half* bd = Bsb[buf];
            #pragma unroll
            for (int i = 0; i < 2; ++i) {
                int c = t + i * 256;
                int r = c >> 2, col = (c & 3) * 8;
                unsigned s = (unsigned)__cvta_generic_to_shared(ad + r * HAP + col);
                const __half* g = A + (size_t)(m0 + r) * K + k0 + col;
                asm volatile("cp.async.ca.shared.global [%0], [%1], 16;\n"
                             :: "r"(s), "l"(g));
            }
            #pragma unroll
            for (int i = 0; i < 2; ++i) {
                int c = t + i * 256;
                int r = c >> 4, col = (c & 15) * 8;
                unsigned s = (unsigned)__cvta_generic_to_shared(bd + r * HBP + col);
                const __half* g = Bm + (size_t)(k0 + r) * N + n0 + col;
                asm volatile("cp.async.ca.shared.global [%0], [%1], 16;\n"
                             :: "r"(s), "l"(g));
            }
            asm volatile("cp.async.commit_group;\n");
        }
        if (tile == 0) continue;
        if (tile < NT) asm volatile("cp.async.wait_group 1;\n");
        else           asm volatile("cp.async.wait_group 0;\n");
        __syncthreads();

        const int buf = (tile - 1) & 1;
        const unsigned ab = (unsigned)__cvta_generic_to_shared(Asb[buf]);
        const unsigned bb = (unsigned)__cvta_generic_to_shared(Bsb[buf]);
        #pragma unroll
        for (int ks = 0; ks < 2; ++ks) {
            const int kk = ks * 16;
            unsigned af[4][4];
            #pragma unroll
            for (int mf = 0; mf < 4; ++mf)
                ldsm_x4(af[mf][0], af[mf][1], af[mf][2], af[mf][3],
                        ab + (unsigned)((wm * 64 + mf * 16 + a_row) * HAP
                                        + kk + a_csel) * 2);
            #pragma unroll
            for (int pr = 0; pr < 2; ++pr) {
                const int nn = wn * 32 + pr * 16;
                unsigned b0, b1, b2, b3;
                ldsm_x4t(b0, b1, b2, b3,
                         bb + (unsigned)((kk + a_row) * HBP + nn + a_csel) * 2);
                #pragma unroll
                for (int mf = 0; mf < 4; ++mf) {
                    mma_f16(acc[mf][pr * 2],     af[mf][0], af[mf][1],
                            af[mf][2], af[mf][3], b0, b1);
                    mma_f16(acc[mf][pr * 2 + 1], af[mf][0], af[mf][1],
                            af[mf][2], af[mf][3], b2, b3);
                }
            }
        }
        __syncthreads();
    }

    #pragma unroll
    for (int mf = 0; mf < 4; ++mf) {
        int r0 = m0 + wm * 64 + mf * 16 + gid;
        #pragma unroll
        for (int nf = 0; nf < 4; ++nf) {
            int c = n0 + wn * 32 + nf * 8 + tig * 2;
            float b0v = bias[c], b1v = bias[c + 1];
            if constexpr (sizeof(OT) == 2) {
                *(__half2*)(C + (size_t)r0 * N + c) =
                    __floats2half2_rn(acc[mf][nf][0] + b0v, acc[mf][nf][1] + b1v);
                *(__half2*)(C + (size_t)(r0 + 8) * N + c) =
                    __floats2half2_rn(acc[mf][nf][2] + b0v, acc[mf][nf][3] + b1v);
            } else {
                float2 v0 = make_float2(acc[mf][nf][0] + b0v, acc[mf][nf][1] + b1v);
                float2 v1 = make_float2(acc[mf][nf][2] + b0v, acc[mf][nf][3] + b1v);
                *(float2*)(C + (size_t)r0 * N + c)       = v0;
                *(float2*)(C + (size_t)(r0 + 8) * N + c) = v1;
            }
        }
    }
}

// ============================================================================
// FlashAttention-2 style causal attention, fp16 mma, register-resident P.
// CTA = 128 q-rows of one (b,h); 8 warps x 16 q-rows; 64-key tiles,
// double-buffered K/V via cp.async; warp-local online softmax (shfl over the
// 4 lanes owning each row); P fragments built in registers (C->A identity).
// ============================================================================
#define TP 72
#define KVBUF (64 * TP)
#define ATT2_SMEM (4 * KVBUF * 2)   /* K0,K1,V0,V1: 36864 B */

__global__ __launch_bounds__(256) void attn_fa2_kernel(
    const __half* __restrict__ gQ, const __half* __restrict__ gK,
    const __half* __restrict__ gV, __half* __restrict__ gZ)
{
    extern __shared__ char smraw[];
    __half* KV = (__half*)smraw;     // [K0 | K1 | V0 | V1], each 64*TP halves
    const unsigned kvb = (unsigned)__cvta_generic_to_shared(KV);

    const int t    = threadIdx.x;
    const int warp = t >> 5, lane = t & 31;
    const int gid  = lane >> 2, tig = lane & 3;
    const int q0   = blockIdx.x * 128;
    const int qw   = q0 + warp * 16;               // warp's first q row
    const int b    = blockIdx.y >> 4;
    const int h    = blockIdx.y & 15;
    const size_t base = (size_t)b * Sz * Hz * DHz + (size_t)h * DHz;
    const int rs   = Hz * DHz;                     // 1024

    // ldmatrix lane address components (validated R12/R13)
    const int a_row  = (lane & 7) + ((lane >> 3) & 1) * 8;
    const int a_csel = ((lane >> 4) & 1) * 8;
    const int b_row  = (lane & 7) + ((lane >> 4) & 1) * 8;
    const int b_csel = ((lane >> 3) & 1) * 8;

    // ---- stage Q (128 x 64) through K-buffer region, load to registers ----
    {
        #pragma unroll
        for (int i = 0; i < 4; ++i) {              // 1024 chunks of 16B
            int c = t + i * 256;
            int r = c >> 3, col = (c & 7) * 8;
            unsigned d = kvb + (unsigned)(r * TP + col) * 2;
            const __half* g = gQ + base + (size_t)(q0 + r) * rs + col;
            asm volatile("cp.async.ca.shared.global [%0], [%1], 16;\n"
                         :: "r"(d), "l"(g));
        }
        asm volatile("cp.async.commit_group;\n");
        asm volatile("cp.async.wait_group 0;\n");
        __syncthreads();
    }
    unsigned qf[4][4];
    #pragma unroll
    for (int ks = 0; ks < 4; ++ks)
        ldsm_x4(qf[ks][0], qf[ks][1], qf[ks][2], qf[ks][3],
                kvb + (unsigned)((warp * 16 + a_row) * TP + ks * 16 + a_csel) * 2);
    __syncthreads();                                // Q reads done before K loads

    // ---- online-softmax state (rows gid, gid+8; replicated over tig) ----
    float m0 = -1e30f, m1 = -1e30f, l0 = 0.f, l1 = 0.f;
    float acco[8][4] = {};                          // 8 dh-tiles of m16n8

    const int ntiles = (q0 >> 6) + 2;

    // issue tile 0
    #pragma unroll
    for (int i = 0; i < 2; ++i) {
        int c = t + i * 256;                        // 512 chunks each
        int r = c >> 3, col = (c & 7) * 8;
        unsigned off = (unsigned)(r * TP + col) * 2;
        const __half* sk = gK + base + (size_t)r * rs + col;
        const __half* sv = gV + base + (size_t)r * rs + col;
        asm volatile("cp.async.ca.shared.global [%0], [%1], 16;\n"
                     :: "r"(kvb + off), "l"(sk));
        asm volatile("cp.async.ca.shared.global [%0], [%1], 16;\n"
                     :: "r"(kvb + (unsigned)(2 * KVBUF) * 2 + off), "l"(sv));
    }
    asm volatile("cp.async.commit_group;\n");

    for (int kt = 0; kt < ntiles; ++kt) {
        asm volatile("cp.async.wait_group 0;\n");
        __syncthreads();

        if (kt + 1 < ntiles) {                      // prefetch next tile
            const int kn = (kt + 1) << 6;
            const int nb = (kt + 1) & 1;
            #pragma unroll
            for (int i = 0; i < 2; ++i) {
                int c = t + i * 256;
                int r = c >> 3, col = (c & 7) * 8;
                unsigned off = (unsigned)(nb * KVBUF + r * TP + col) * 2;
                const __half* sk = gK + base + (size_t)(kn + r) * rs + col;
                const __half* sv = gV + base + (size_t)(kn + r) * rs + col;
                asm volatile("cp.async.ca.shared.global [%0], [%1], 16;\n"
                             :: "r"(kvb + off), "l"(sk));
                asm volatile("cp.async.ca.shared.global [%0], [%1], 16;\n"
                             :: "r"(kvb + (unsigned)(2 * KVBUF) * 2 + off), "l"(sv));
            }
            asm volatile("cp.async.commit_group;\n");
        }

        const int k0 = kt << 6;
        if (k0 <= qw + 15) {                        // warp-causal gate
            const unsigned kb = kvb + (unsigned)((kt & 1) * KVBUF) * 2;
            const unsigned vb = kvb + (unsigned)((2 + (kt & 1)) * KVBUF) * 2;

            // ---- S = Q @ K^T : 8 n-tiles (8 keys each) ----
            float accs[8][4] = {};
            #pragma unroll
            for (int ks = 0; ks < 4; ++ks) {
                #pragma unroll
                for (int nt2 = 0; nt2 < 4; ++nt2) {
                    unsigned b0, b1, b2, b3;
                    ldsm_x4(b0, b1, b2, b3,
                            kb + (unsigned)((nt2 * 16 + b_row) * TP
                                            + ks * 16 + b_csel) * 2);
                    mma_f16(accs[nt2 * 2],     qf[ks][0], qf[ks][1],
                            qf[ks][2], qf[ks][3], b0, b1);
                    mma_f16(accs[nt2 * 2 + 1], qf[ks][0], qf[ks][1],
                            qf[ks][2], qf[ks][3], b2, b3);
                }
            }
            // ---- scale + causal mask (in registers) ----
            const int qg0 = qw + gid, qg1 = qw + gid + 8;
            #pragma unroll
            for (int j = 0; j < 8; ++j) {
                int kg = k0 + j * 8 + tig * 2;
                accs[j][0] = (kg     > qg0) ? -1e30f : accs[j][0] * 0.125f;
                accs[j][1] = (kg + 1 > qg0) ? -1e30f : accs[j][1] * 0.125f;
                accs[j][2] = (kg     > qg1) ? -1e30f : accs[j][2] * 0.125f;
                accs[j][3] = (kg + 1 > qg1) ? -1e30f : accs[j][3] * 0.125f;
            }
            // ---- warp-local online softmax ----
            float mx0 = -1e30f, mx1 = -1e30f;
            #pragma unroll
            for (int j = 0; j < 8; ++j) {
                mx0 = fmaxf(mx0, fmaxf(accs[j][0], accs[j][1]));
                mx1 = fmaxf(mx1, fmaxf(accs[j][2], accs[j][3]));
            }
            mx0 = fmaxf(mx0, __shfl_xor_sync(0xffffffffu, mx0, 1));
            mx0 = fmaxf(mx0, __shfl_xor_sync(0xffffffffu, mx0, 2));
            mx1 = fmaxf(mx1, __shfl_xor_sync(0xffffffffu, mx1, 1));
            mx1 = fmaxf(mx1, __shfl_xor_sync(0xffffffffu, mx1, 2));
            const float mn0 = fmaxf(m0, mx0), mn1 = fmaxf(m1, mx1);
            const float cr0 = __expf(m0 - mn0), cr1 = __expf(m1 - mn1);

            unsigned p01[8], p23[8];
            float s0 = 0.f, s1 = 0.f;
            #pragma unroll
            for (int j = 0; j < 8; ++j) {
                float p0 = __expf(accs[j][0] - mn0);
                float p1 = __expf(accs[j][1] - mn0);
                float p2 = __expf(accs[j][2] - mn1);
                float p3 = __expf(accs[j][3] - mn1);
                s0 += p0 + p1; s1 += p2 + p3;
                __half2 h01 = __floats2half2_rn(p0, p1);
                __half2 h23 = __floats2half2_rn(p2, p3);
                p01[j] = *(unsigned*)&h01;
                p23[j] = *(unsigned*)&h23;
            }
            s0 += __shfl_xor_sync(0xffffffffu, s0, 1);
            s0 += __shfl_xor_sync(0xffffffffu, s0, 2);
            s1 += __shfl_xor_sync(0xffffffffu, s1, 1);
            s1 += __shfl_xor_sync(0xffffffffu, s1, 2);
            l0 = l0 * cr0 + s0;  l1 = l1 * cr1 + s1;
            m0 = mn0;            m1 = mn1;

            // ---- O = O*corr + P @ V (P fragments direct from registers) ----
            #pragma unroll
            for (int j = 0; j < 8; ++j) {
                acco[j][0] *= cr0; acco[j][1] *= cr0;
                acco[j][2] *= cr1; acco[j][3] *= cr1;
            }
            #pragma unroll
            for (int ks = 0; ks < 4; ++ks) {        // key chunks of 16
                unsigned a0 = p01[ks * 2],     a1 = p23[ks * 2];
                unsigned a2 = p01[ks * 2 + 1], a3 = p23[ks * 2 + 1];
                int vrow = ks * 16 + (lane & 7) + ((lane >> 3) & 1) * 8;
                #pragma unroll
                for (int dt2 = 0; dt2 < 4; ++dt2) {
                    int vcol = dt2 * 16 + (((lane >> 4) & 1) << 3);
                    unsigned b0, b1, b2, b3;
                    ldsm_x4t(b0, b1, b2, b3,
                             vb + (unsigned)(vrow * TP + vcol) * 2);
                    mma_f16(acco[dt2 * 2],     a0, a1, a2, a3, b0, b1);
                    mma_f16(acco[dt2 * 2 + 1], a0, a1, a2, a3, b2, b3);
                }
            }
        }
    }

    // ---- normalize + store (half) ----
    {
        const float inv0 = 1.f / l0, inv1 = 1.f / l1;
        const int r0 = qw + gid, r1 = qw + gid + 8;
        #pragma unroll
        for (int j = 0; j < 8; ++j) {
            int c = j * 8 + tig * 2;
            *(__half2*)(gZ + base + (size_t)r0 * rs + c) =
                __floats2half2_rn(acco[j][0] * inv0, acco[j][1] * inv0);
            *(__half2*)(gZ + base + (size_t)r1 * rs + c) =
                __floats2half2_rn(acco[j][2] * inv1, acco[j][3] * inv1);
        }
    }
}

// ============================================================================
extern "C" void kernel_launch(void* const* d_in, const int* in_sizes, int n_in,
                              void* d_out, int out_size)
{
    (void)in_sizes; (void)n_in; (void)out_size;
    const float* x  = (const float*)d_in[0];
    const float* WQ = (const float*)d_in[1];
    const float* bQ = (const float*)d_in[2];
    const float* WK = (const float*)d_in[3];
    const float* bK = (const float*)d_in[4];
    const float* WV = (const float*)d_in[5];
    const float* bV = (const float*)d_in[6];
    const float* WO = (const float*)d_in[7];
    const float* bO = (const float*)d_in[8];
    float* out = (float*)d_out;

    __half *pXh, *pWq, *pWk, *pWv, *pWo, *pQ, *pK, *pV, *pZ;
    cudaGetSymbolAddress((void**)&pXh, g_Xh);
    cudaGetSymbolAddress((void**)&pWq, g_Wq);
    cudaGetSymbolAddress((void**)&pWk, g_Wk);
    cudaGetSymbolAddress((void**)&pWv, g_Wv);
    cudaGetSymbolAddress((void**)&pWo, g_Wo);
    cudaGetSymbolAddress((void**)&pQ,  g_Q);
    cudaGetSymbolAddress((void**)&pK,  g_K);
    cudaGetSymbolAddress((void**)&pV,  g_V);
    cudaGetSymbolAddress((void**)&pZ,  g_Zh);

    cudaFuncSetAttribute((const void*)f16_gemm<__half>,
                         cudaFuncAttributeMaxDynamicSharedMemorySize, HGEMM_SMEM);
    cudaFuncSetAttribute((const void*)f16_gemm<float>,
                         cudaFuncAttributeMaxDynamicSharedMemorySize, HGEMM_SMEM);
    cudaFuncSetAttribute((const void*)attn_fa2_kernel,
                         cudaFuncAttributeMaxDynamicSharedMemorySize, ATT2_SMEM);

    // ---- conversions ----
    const int NX = BSz * Dz;                  // 8388608
    cvt_f2h<<<NX / 4 / 256, 256>>>(x, pXh, NX);
    cvt_w_proj<<<1024, 256>>>(WQ, pWq);
    cvt_w_proj<<<1024, 256>>>(WK, pWk);
    cvt_w_proj<<<1024, 256>>>(WV, pWv);
    const int NW = Hz * DHz * Dz;             // 1048576 (W_O already [k][n])
    cvt_f2h<<<NW / 4 / 256, 256>>>(WO, pWo, NW);

    // ---- projections ----
    dim3 blk(256);
    dim3 gproj((Hz * DHz) / 128, BSz / 128);  // 8 x 64
    f16_gemm<__half><<<gproj, blk, HGEMM_SMEM>>>(pXh, pWq, bQ, pQ, BSz, Hz * DHz, Dz);
    f16_gemm<__half><<<gproj, blk, HGEMM_SMEM>>>(pXh, pWk, bK, pK, BSz, Hz * DHz, Dz);
    f16_gemm<__half><<<gproj, blk, HGEMM_SMEM>>>(pXh, pWv, bV, pV, BSz, Hz * DHz, Dz);

    // ---- attention (FA2-style, 128 q-rows per CTA) ----
    attn_fa2_kernel<<<dim3(Sz / 128, Bz * Hz), blk, ATT2_SMEM>>>(pQ, pK, pV, pZ);

    // ---- output projection ----
    dim3 gout(Dz / 128, BSz / 128);           // 8 x 64
    f16_gemm<float><<<gout, blk, HGEMM_SMEM>>>(pZ, pWo, bO, out, BSz, Dz, Hz * DHz);
}